// round 3
// baseline (speedup 1.0000x reference)
#include <cuda_runtime.h>
#include <cstdint>
#include <cstddef>

#define BB 8
#define TT 512
#define HH 512
#define VV 32000
#define PP 20
#define G4H 2048
#define G4P 80
#define MTOK (BB*TT)   // 4096

// ---------------- scratch (static device globals; no allocations anywhere) ----------------
__device__ float d_emb[MTOK*HH];          // gathered embeddings [4096,512]
__device__ float d_xg_enc[MTOK*G4H];      // encoder input gates [4096,2048]
__device__ float d_henc[MTOK*HH];         // encoder hidden outputs [B*T,512]
__device__ float d_hglob[BB*HH];          // current encoder h
__device__ float d_cstate[BB*HH];         // current encoder c
__device__ float d_xg_pos[MTOK*G4P];      // pos lstm input gates [4096,80]
__device__ float d_mu[BB*TT];
__device__ float d_sg[BB*TT];
__device__ float d_gw[(size_t)BB*TT*TT];  // normalized attention weights [8,512,512]
__device__ float d_ctx[MTOK*HH];
__device__ float d_cat[MTOK*2*HH];
__device__ float d_comb[MTOK*HH];

__device__ __forceinline__ float sigmoidf_(float x) { return 1.f / (1.f + __expf(-x)); }

// ---------------- embedding gather ----------------
__global__ void gather_kernel(const int* __restrict__ tokens, const float* __restrict__ emb) {
    int m = blockIdx.x;
    int tok = tokens[m];
    const float4* src = reinterpret_cast<const float4*>(emb + (size_t)tok * HH);
    float4* dst = reinterpret_cast<float4*>(d_emb + (size_t)m * HH);
    dst[threadIdx.x] = src[threadIdx.x];   // 128 threads * float4 = 512 floats
}

// ---------------- generic SGEMM: C = act(A[M,K] @ W[N,K]^T + b1 + b2) ----------------
// BM=BN=128, BK=8, 256 threads, 8x8 per thread.
template<int ACT, bool GUARD>
__global__ __launch_bounds__(256) void gemm_nt_kernel(
    const float* __restrict__ A, const float* __restrict__ W,
    const float* __restrict__ b1, const float* __restrict__ b2,
    float* __restrict__ C, int M, int N, int K)
{
    __shared__ float As[8][132];
    __shared__ float Ws[8][132];
    int tid = threadIdx.x;
    int m0 = blockIdx.y * 128, n0 = blockIdx.x * 128;
    int lrow = tid >> 1;
    int lk = (tid & 1) * 4;
    bool a_ok = !GUARD || (m0 + lrow) < M;
    bool w_ok = !GUARD || (n0 + lrow) < N;
    const float* Aptr = A + (size_t)(m0 + lrow) * K + lk;
    const float* Wptr = W + (size_t)(n0 + lrow) * K + lk;
    int tm = (tid >> 4) * 8;
    int tn = (tid & 15) * 8;

    float acc[8][8];
#pragma unroll
    for (int i = 0; i < 8; i++)
#pragma unroll
        for (int j = 0; j < 8; j++) acc[i][j] = 0.f;

    for (int kt = 0; kt < K; kt += 8) {
        float4 av = a_ok ? *reinterpret_cast<const float4*>(Aptr + kt) : make_float4(0,0,0,0);
        float4 wv = w_ok ? *reinterpret_cast<const float4*>(Wptr + kt) : make_float4(0,0,0,0);
        __syncthreads();
        As[lk+0][lrow] = av.x; As[lk+1][lrow] = av.y; As[lk+2][lrow] = av.z; As[lk+3][lrow] = av.w;
        Ws[lk+0][lrow] = wv.x; Ws[lk+1][lrow] = wv.y; Ws[lk+2][lrow] = wv.z; Ws[lk+3][lrow] = wv.w;
        __syncthreads();
#pragma unroll
        for (int k = 0; k < 8; k++) {
            float a[8], b[8];
            *reinterpret_cast<float4*>(&a[0]) = *reinterpret_cast<float4*>(&As[k][tm]);
            *reinterpret_cast<float4*>(&a[4]) = *reinterpret_cast<float4*>(&As[k][tm+4]);
            *reinterpret_cast<float4*>(&b[0]) = *reinterpret_cast<float4*>(&Ws[k][tn]);
            *reinterpret_cast<float4*>(&b[4]) = *reinterpret_cast<float4*>(&Ws[k][tn+4]);
#pragma unroll
            for (int i = 0; i < 8; i++)
#pragma unroll
                for (int j = 0; j < 8; j++) acc[i][j] += a[i] * b[j];
        }
    }

    float bias[8];
#pragma unroll
    for (int j = 0; j < 8; j++) {
        int gn = n0 + tn + j;
        float bv = 0.f;
        if (!GUARD || gn < N) {
            if (b1) bv += b1[gn];
            if (b2) bv += b2[gn];
        }
        bias[j] = bv;
    }

    if (!GUARD) {
#pragma unroll
        for (int i = 0; i < 8; i++) {
            float* crow = C + (size_t)(m0 + tm + i) * N + n0 + tn;
#pragma unroll
            for (int j4 = 0; j4 < 2; j4++) {
                float4 v;
                float v0 = acc[i][j4*4+0] + bias[j4*4+0];
                float v1 = acc[i][j4*4+1] + bias[j4*4+1];
                float v2 = acc[i][j4*4+2] + bias[j4*4+2];
                float v3 = acc[i][j4*4+3] + bias[j4*4+3];
                if (ACT == 1) { v0 = tanhf(v0); v1 = tanhf(v1); v2 = tanhf(v2); v3 = tanhf(v3); }
                v.x = v0; v.y = v1; v.z = v2; v.w = v3;
                *reinterpret_cast<float4*>(&crow[j4*4]) = v;
            }
        }
    } else {
#pragma unroll
        for (int i = 0; i < 8; i++) {
            int gm = m0 + tm + i;
            if (gm >= M) continue;
#pragma unroll
            for (int j = 0; j < 8; j++) {
                int gn = n0 + tn + j;
                if (gn >= N) continue;
                float v = acc[i][j] + bias[j];
                if (ACT == 1) v = tanhf(v);
                C[(size_t)gm * N + gn] = v;
            }
        }
    }
}

// ---------------- batched SGEMM: C[z] = A[z][M,K] @ B[z][K,N], B row-major [K,N] ----------------
__global__ __launch_bounds__(256) void gemm_nn_kernel(
    const float* __restrict__ Ab, const float* __restrict__ Bb, float* __restrict__ Cb,
    int M, int N, int K, size_t sA, size_t sB, size_t sC)
{
    __shared__ float As[8][132];
    __shared__ float Ws[8][132];
    const float* A = Ab + blockIdx.z * sA;
    const float* Bm = Bb + blockIdx.z * sB;
    float* C = Cb + blockIdx.z * sC;
    int tid = threadIdx.x;
    int m0 = blockIdx.y * 128, n0 = blockIdx.x * 128;
    int lrow = tid >> 1;
    int lk = (tid & 1) * 4;
    int bk = tid >> 5;            // 0..7
    int bn = (tid & 31) * 4;      // 0..124
    int tm = (tid >> 4) * 8;
    int tn = (tid & 15) * 8;

    float acc[8][8];
#pragma unroll
    for (int i = 0; i < 8; i++)
#pragma unroll
        for (int j = 0; j < 8; j++) acc[i][j] = 0.f;

    for (int kt = 0; kt < K; kt += 8) {
        float4 av = *reinterpret_cast<const float4*>(A + (size_t)(m0 + lrow) * K + kt + lk);
        float4 bv = *reinterpret_cast<const float4*>(Bm + (size_t)(kt + bk) * N + n0 + bn);
        __syncthreads();
        As[lk+0][lrow] = av.x; As[lk+1][lrow] = av.y; As[lk+2][lrow] = av.z; As[lk+3][lrow] = av.w;
        *reinterpret_cast<float4*>(&Ws[bk][bn]) = bv;
        __syncthreads();
#pragma unroll
        for (int k = 0; k < 8; k++) {
            float a[8], b[8];
            *reinterpret_cast<float4*>(&a[0]) = *reinterpret_cast<float4*>(&As[k][tm]);
            *reinterpret_cast<float4*>(&a[4]) = *reinterpret_cast<float4*>(&As[k][tm+4]);
            *reinterpret_cast<float4*>(&b[0]) = *reinterpret_cast<float4*>(&Ws[k][tn]);
            *reinterpret_cast<float4*>(&b[4]) = *reinterpret_cast<float4*>(&Ws[k][tn+4]);
#pragma unroll
            for (int i = 0; i < 8; i++)
#pragma unroll
                for (int j = 0; j < 8; j++) acc[i][j] += a[i] * b[j];
        }
    }
#pragma unroll
    for (int i = 0; i < 8; i++) {
        float* crow = C + (size_t)(m0 + tm + i) * N + n0 + tn;
#pragma unroll
        for (int j4 = 0; j4 < 2; j4++) {
            float4 v;
            v.x = acc[i][j4*4+0]; v.y = acc[i][j4*4+1];
            v.z = acc[i][j4*4+2]; v.w = acc[i][j4*4+3];
            *reinterpret_cast<float4*>(&crow[j4*4]) = v;
        }
    }
}

// ---------------- encoder LSTM: one launch per timestep (no grid sync, cannot hang) ----------------
__global__ void enc_init_kernel() {
    int i = blockIdx.x * blockDim.x + threadIdx.x;
    if (i < BB * HH) { d_hglob[i] = 0.f; d_cstate[i] = 0.f; }
}

// grid = 128 CTAs x 256 threads. CTA c owns hidden indices [c*4, c*4+4) -> 16 gate rows.
// Warp w handles local rows {2w, 2w+1}; lanes split K (conflict-free interleave).
__global__ __launch_bounds__(256) void enc_step_kernel(
    int t, const float* __restrict__ xg, const float* __restrict__ Whh)
{
    __shared__ float h_s[BB * HH];     // 16 KB, flat [b*512 + k]
    __shared__ float red_s[16][8];
    int tid = threadIdx.x, cid = blockIdx.x;
    int lane = tid & 31, w = tid >> 5;

    // load h (all 4096 floats) into smem, coalesced float4
#pragma unroll
    for (int i = 0; i < 4; i++) {
        int idx = i * 256 + tid;
        reinterpret_cast<float4*>(h_s)[idx] = reinterpret_cast<const float4*>(d_hglob)[idx];
    }
    __syncthreads();

    // row pointers for this warp's two gate rows
    int rl0 = w * 2, rl1 = w * 2 + 1;
    const float* wrow0 = Whh + (size_t)((rl0 >> 2) * HH + cid * 4 + (rl0 & 3)) * HH;
    const float* wrow1 = Whh + (size_t)((rl1 >> 2) * HH + cid * 4 + (rl1 & 3)) * HH;

    float acc0[8], acc1[8];
#pragma unroll
    for (int b = 0; b < 8; b++) { acc0[b] = 0.f; acc1[b] = 0.f; }

#pragma unroll
    for (int it = 0; it < 4; it++) {
        int k0 = it * 128 + lane * 4;
        float4 w0 = *reinterpret_cast<const float4*>(wrow0 + k0);
        float4 w1 = *reinterpret_cast<const float4*>(wrow1 + k0);
#pragma unroll
        for (int b = 0; b < 8; b++) {
            float4 hv = *reinterpret_cast<const float4*>(&h_s[b * HH + k0]);
            acc0[b] += w0.x*hv.x + w0.y*hv.y + w0.z*hv.z + w0.w*hv.w;
            acc1[b] += w1.x*hv.x + w1.y*hv.y + w1.z*hv.z + w1.w*hv.w;
        }
    }
    // warp reductions
#pragma unroll
    for (int b = 0; b < 8; b++) {
        float v0 = acc0[b], v1 = acc1[b];
#pragma unroll
        for (int o = 16; o; o >>= 1) {
            v0 += __shfl_xor_sync(0xffffffffu, v0, o);
            v1 += __shfl_xor_sync(0xffffffffu, v1, o);
        }
        if (lane == 0) { red_s[rl0][b] = v0; red_s[rl1][b] = v1; }
    }
    __syncthreads();

    if (tid < 32) {
        int b = tid >> 2, j2 = tid & 3;
        float g4[4];
#pragma unroll
        for (int q = 0; q < 4; q++)
            g4[q] = xg[((size_t)(b*TT + t))*G4H + q*HH + cid*4 + j2] + red_s[q*4 + j2][b];
        float ii = sigmoidf_(g4[0]);
        float ff = sigmoidf_(g4[1]);
        float gg = tanhf(g4[2]);
        float oo = sigmoidf_(g4[3]);
        int hidx = cid*4 + j2;
        float c = ff * d_cstate[b*HH + hidx] + ii * gg;
        float h = oo * tanhf(c);
        d_cstate[b*HH + hidx] = c;
        d_hglob[b*HH + hidx]  = h;
        d_henc[((size_t)(b*TT + t))*HH + hidx] = h;
    }
}

// ---------------- pos LSTM + mu/sigma heads + mu scan (single CTA) ----------------
__global__ void pos_kernel(const int* __restrict__ pad_len,
                           const float* __restrict__ Whh,
                           const float* __restrict__ Wmu, const float* __restrict__ bmu,
                           const float* __restrict__ Wsig, const float* __restrict__ bsig)
{
    __shared__ float Whh_s[G4P][PP];
    __shared__ float Wmu_s[3][PP];
    __shared__ float Wsig_s[PP];
    __shared__ float hp[BB][PP], cp[BB][PP], gate_s[BB][G4P];
    __shared__ float mu_prev[BB];
    int tid = threadIdx.x;
    for (int i = tid; i < G4P*PP; i += blockDim.x) Whh_s[i/PP][i%PP] = Whh[i];
    for (int i = tid; i < 3*PP;  i += blockDim.x) Wmu_s[i/PP][i%PP] = Wmu[i];
    if (tid < PP) Wsig_s[tid] = Wsig[tid];
    for (int i = tid; i < BB*PP; i += blockDim.x) { hp[i/PP][i%PP] = 0.f; cp[i/PP][i%PP] = 0.f; }
    if (tid < BB) mu_prev[tid] = 0.f;
    __syncthreads();

    for (int t = 0; t < TT; t++) {
        if (tid < BB * G4P) {
            int b = tid / G4P, r = tid % G4P;
            float acc = d_xg_pos[((size_t)(b*TT + t))*G4P + r];
#pragma unroll
            for (int k = 0; k < PP; k++) acc += Whh_s[r][k] * hp[b][k];
            gate_s[b][r] = acc;
        }
        __syncthreads();
        if (tid < BB * PP) {
            int b = tid / PP, j = tid % PP;
            float ii = sigmoidf_(gate_s[b][j]);
            float ff = sigmoidf_(gate_s[b][PP + j]);
            float gg = tanhf(gate_s[b][2*PP + j]);
            float oo = sigmoidf_(gate_s[b][3*PP + j]);
            float c = ff * cp[b][j] + ii * gg;
            cp[b][j] = c;
            hp[b][j] = oo * tanhf(c);
        }
        __syncthreads();
        if (tid < BB) {
            int b = tid;
            float L = (float)pad_len[b];
            float m3[3];
#pragma unroll
            for (int g = 0; g < 3; g++) {
                float s = bmu[g];
#pragma unroll
                for (int p = 0; p < PP; p++) s += hp[b][p] * Wmu_s[g][p];
                m3[g] = fmaxf(s, 0.f);
            }
            float ss = bsig[0];
#pragma unroll
            for (int p = 0; p < PP; p++) ss += hp[b][p] * Wsig_s[p];
            float sgv = sigmoidf_(ss);
            float mu = m3[0]*mu_prev[b] + m3[1]/L + m3[2]*((float)(t+1))/L;
            mu = fmaxf(mu, (float)t / L);
            mu_prev[b] = mu;
            d_mu[b*TT + t] = mu;
            d_sg[b*TT + t] = sgv;
        }
        __syncthreads();
    }
}

// ---------------- normalized Gaussian prefix weights: one warp per (b, tq) ----------------
__global__ void attn_kernel(const int* __restrict__ pad_len) {
    int wq = blockIdx.x * 8 + (threadIdx.x >> 5);
    int lane = threadIdx.x & 31;
    int b = wq >> 9, tq = wq & 511;
    float L = (float)pad_len[b];
    float mu = d_mu[b*TT + tq], sg = d_sg[b*TT + tq];
    float denom = 2.f * sg * sg + 0.001f;
    float* grow = &d_gw[((size_t)(b*TT + tq)) * TT];
    float wv[16];
    float sum = 0.f;
#pragma unroll
    for (int i = 0; i < 16; i++) {
        int tk = lane + i*32;
        float dd = (float)tk / L - mu;
        float v = (tk <= tq) ? __expf(-dd*dd / denom) : 0.f;
        wv[i] = v; sum += v;
    }
#pragma unroll
    for (int o = 16; o; o >>= 1) sum += __shfl_xor_sync(0xffffffffu, sum, o);
    float inv = 1.f / fmaxf(sum, 1e-12f);
#pragma unroll
    for (int i = 0; i < 16; i++) grow[lane + i*32] = wv[i] * inv;
}

// ---------------- concat [ctx, enc] ----------------
__global__ void concat_kernel() {
    int idx = blockIdx.x * blockDim.x + threadIdx.x;     // float4 index per half
    if (idx >= MTOK * 128) return;
    int m = idx >> 7, h4 = idx & 127;
    float4 c4 = *reinterpret_cast<const float4*>(&d_ctx[((size_t)m << 9) + (h4 << 2)]);
    float4 e4 = *reinterpret_cast<const float4*>(&d_henc[((size_t)m << 9) + (h4 << 2)]);
    *reinterpret_cast<float4*>(&d_cat[(size_t)m*1024 + (h4 << 2)]) = c4;
    *reinterpret_cast<float4*>(&d_cat[(size_t)m*1024 + 512 + (h4 << 2)]) = e4;
}

// ---------------- launcher ----------------
extern "C" void kernel_launch(void* const* d_in, const int* in_sizes, int n_in,
                              void* d_out, int out_size)
{
    const int*   tokens   = (const int*)d_in[0];
    const int*   pad_len  = (const int*)d_in[1];
    const float* embedding= (const float*)d_in[2];
    const float* enc_Wih  = (const float*)d_in[3];
    const float* enc_Whh  = (const float*)d_in[4];
    const float* enc_bih  = (const float*)d_in[5];
    const float* enc_bhh  = (const float*)d_in[6];
    const float* pos_Wih  = (const float*)d_in[7];
    const float* pos_Whh  = (const float*)d_in[8];
    const float* pos_bih  = (const float*)d_in[9];
    const float* pos_bhh  = (const float*)d_in[10];
    const float* W_mu     = (const float*)d_in[11];
    const float* b_mu     = (const float*)d_in[12];
    const float* W_sig    = (const float*)d_in[13];
    const float* b_sig    = (const float*)d_in[14];
    const float* W_cat    = (const float*)d_in[15];
    const float* b_cat    = (const float*)d_in[16];
    const float* dec_b    = (const float*)d_in[17];
    float* out = (float*)d_out;

    float *p_emb, *p_xg_enc, *p_henc, *p_xg_pos, *p_gw, *p_ctx, *p_cat, *p_comb;
    cudaGetSymbolAddress((void**)&p_emb,    d_emb);
    cudaGetSymbolAddress((void**)&p_xg_enc, d_xg_enc);
    cudaGetSymbolAddress((void**)&p_henc,   d_henc);
    cudaGetSymbolAddress((void**)&p_xg_pos, d_xg_pos);
    cudaGetSymbolAddress((void**)&p_gw,     d_gw);
    cudaGetSymbolAddress((void**)&p_ctx,    d_ctx);
    cudaGetSymbolAddress((void**)&p_cat,    d_cat);
    cudaGetSymbolAddress((void**)&p_comb,   d_comb);

    // 1) gather embeddings
    gather_kernel<<<MTOK, 128>>>(tokens, embedding);
    // 2) xg_enc = emb @ enc_Wih^T + bih + bhh   [4096,2048]
    gemm_nt_kernel<0,false><<<dim3(G4H/128, MTOK/128), 256>>>(
        p_emb, enc_Wih, enc_bih, enc_bhh, p_xg_enc, MTOK, G4H, HH);
    // 3) encoder LSTM: init + 512 sequential step launches
    enc_init_kernel<<<(BB*HH + 255)/256, 256>>>();
    for (int t = 0; t < TT; t++)
        enc_step_kernel<<<128, 256>>>(t, p_xg_enc, enc_Whh);
    // 4) xg_pos = henc @ pos_Wih^T + biases   [4096,80]
    gemm_nt_kernel<0,true><<<dim3(1, MTOK/128), 256>>>(
        p_henc, pos_Wih, pos_bih, pos_bhh, p_xg_pos, MTOK, G4P, HH);
    // 5) pos LSTM + heads + mu scan
    pos_kernel<<<1, 640>>>(pad_len, pos_Whh, W_mu, b_mu, W_sig, b_sig);
    // 6) attention weights (normalized)
    attn_kernel<<<(BB*TT)/8, 256>>>(pad_len);
    // 7) ctx = g @ enc (batched over b)
    gemm_nn_kernel<<<dim3(HH/128, TT/128, BB), 256>>>(
        p_gw, p_henc, p_ctx, TT, HH, TT,
        (size_t)TT*TT, (size_t)TT*HH, (size_t)TT*HH);
    // 8) concat
    concat_kernel<<<(MTOK*128)/256, 256>>>();
    // 9) comb = tanh(cat @ W_cat^T + b_cat)
    gemm_nt_kernel<1,false><<<dim3(HH/128, MTOK/128), 256>>>(
        p_cat, W_cat, b_cat, nullptr, p_comb, MTOK, HH, 2*HH);
    // 10) logits = comb @ embedding^T + dec_b  -> d_out
    gemm_nt_kernel<0,false><<<dim3(VV/128, MTOK/128), 256>>>(
        p_comb, embedding, dec_b, nullptr, out, MTOK, VV, HH);

    (void)in_sizes; (void)n_in; (void)out_size;
}

// round 4
// speedup vs baseline: 1.0171x; 1.0171x over previous
#include <cuda_runtime.h>
#include <cstdint>
#include <cstddef>

#define BB 8
#define TT 512
#define HH 512
#define VV 32000
#define PP 20
#define G4H 2048
#define G4P 80
#define MTOK (BB*TT)   // 4096
#define ENC_CTAS 128

// ---------------- scratch (static device globals; no allocations anywhere) ----------------
__device__ float d_emb[MTOK*HH];          // gathered embeddings [4096,512]
__device__ float d_xg_enc[MTOK*G4H];      // encoder input gates [4096,2048]
__device__ float d_henc[MTOK*HH];         // encoder hidden outputs [B*T,512]
__device__ float d_hglob[BB*HH];          // current encoder h (step-shared)
__device__ float d_xg_pos[MTOK*G4P];      // pos lstm input gates [4096,80]
__device__ float d_mu[BB*TT];
__device__ float d_sg[BB*TT];
__device__ float d_gw[(size_t)BB*TT*TT];  // normalized attention weights [8,512,512]
__device__ float d_ctx[MTOK*HH];
__device__ float d_cat[MTOK*2*HH];
__device__ float d_comb[MTOK*HH];
__device__ unsigned int d_bar_count = 0;
__device__ unsigned int d_bar_gen = 0;

__device__ __forceinline__ float sigmoidf_(float x) { return 1.f / (1.f + __expf(-x)); }

// ---------------- embedding gather ----------------
__global__ void gather_kernel(const int* __restrict__ tokens, const float* __restrict__ emb) {
    int m = blockIdx.x;
    int tok = tokens[m];
    const float4* src = reinterpret_cast<const float4*>(emb + (size_t)tok * HH);
    float4* dst = reinterpret_cast<float4*>(d_emb + (size_t)m * HH);
    dst[threadIdx.x] = src[threadIdx.x];   // 128 threads * float4 = 512 floats
}

// ---------------- generic SGEMM: C = act(A[M,K] @ W[N,K]^T + b1 + b2) ----------------
// BM=BN=128, BK=8, 256 threads, 8x8 per thread.
template<int ACT, bool GUARD>
__global__ __launch_bounds__(256) void gemm_nt_kernel(
    const float* __restrict__ A, const float* __restrict__ W,
    const float* __restrict__ b1, const float* __restrict__ b2,
    float* __restrict__ C, int M, int N, int K)
{
    __shared__ float As[8][132];
    __shared__ float Ws[8][132];
    int tid = threadIdx.x;
    int m0 = blockIdx.y * 128, n0 = blockIdx.x * 128;
    int lrow = tid >> 1;
    int lk = (tid & 1) * 4;
    bool a_ok = !GUARD || (m0 + lrow) < M;
    bool w_ok = !GUARD || (n0 + lrow) < N;
    const float* Aptr = A + (size_t)(m0 + lrow) * K + lk;
    const float* Wptr = W + (size_t)(n0 + lrow) * K + lk;
    int tm = (tid >> 4) * 8;
    int tn = (tid & 15) * 8;

    float acc[8][8];
#pragma unroll
    for (int i = 0; i < 8; i++)
#pragma unroll
        for (int j = 0; j < 8; j++) acc[i][j] = 0.f;

    for (int kt = 0; kt < K; kt += 8) {
        float4 av = a_ok ? *reinterpret_cast<const float4*>(Aptr + kt) : make_float4(0,0,0,0);
        float4 wv = w_ok ? *reinterpret_cast<const float4*>(Wptr + kt) : make_float4(0,0,0,0);
        __syncthreads();
        As[lk+0][lrow] = av.x; As[lk+1][lrow] = av.y; As[lk+2][lrow] = av.z; As[lk+3][lrow] = av.w;
        Ws[lk+0][lrow] = wv.x; Ws[lk+1][lrow] = wv.y; Ws[lk+2][lrow] = wv.z; Ws[lk+3][lrow] = wv.w;
        __syncthreads();
#pragma unroll
        for (int k = 0; k < 8; k++) {
            float a[8], b[8];
            *reinterpret_cast<float4*>(&a[0]) = *reinterpret_cast<float4*>(&As[k][tm]);
            *reinterpret_cast<float4*>(&a[4]) = *reinterpret_cast<float4*>(&As[k][tm+4]);
            *reinterpret_cast<float4*>(&b[0]) = *reinterpret_cast<float4*>(&Ws[k][tn]);
            *reinterpret_cast<float4*>(&b[4]) = *reinterpret_cast<float4*>(&Ws[k][tn+4]);
#pragma unroll
            for (int i = 0; i < 8; i++)
#pragma unroll
                for (int j = 0; j < 8; j++) acc[i][j] += a[i] * b[j];
        }
    }

    float bias[8];
#pragma unroll
    for (int j = 0; j < 8; j++) {
        int gn = n0 + tn + j;
        float bv = 0.f;
        if (!GUARD || gn < N) {
            if (b1) bv += b1[gn];
            if (b2) bv += b2[gn];
        }
        bias[j] = bv;
    }

    if (!GUARD) {
#pragma unroll
        for (int i = 0; i < 8; i++) {
            float* crow = C + (size_t)(m0 + tm + i) * N + n0 + tn;
#pragma unroll
            for (int j4 = 0; j4 < 2; j4++) {
                float4 v;
                float v0 = acc[i][j4*4+0] + bias[j4*4+0];
                float v1 = acc[i][j4*4+1] + bias[j4*4+1];
                float v2 = acc[i][j4*4+2] + bias[j4*4+2];
                float v3 = acc[i][j4*4+3] + bias[j4*4+3];
                if (ACT == 1) { v0 = tanhf(v0); v1 = tanhf(v1); v2 = tanhf(v2); v3 = tanhf(v3); }
                v.x = v0; v.y = v1; v.z = v2; v.w = v3;
                *reinterpret_cast<float4*>(&crow[j4*4]) = v;
            }
        }
    } else {
#pragma unroll
        for (int i = 0; i < 8; i++) {
            int gm = m0 + tm + i;
            if (gm >= M) continue;
#pragma unroll
            for (int j = 0; j < 8; j++) {
                int gn = n0 + tn + j;
                if (gn >= N) continue;
                float v = acc[i][j] + bias[j];
                if (ACT == 1) v = tanhf(v);
                C[(size_t)gm * N + gn] = v;
            }
        }
    }
}

// ---------------- batched SGEMM: C[z] = A[z][M,K] @ B[z][K,N], B row-major [K,N] ----------------
__global__ __launch_bounds__(256) void gemm_nn_kernel(
    const float* __restrict__ Ab, const float* __restrict__ Bb, float* __restrict__ Cb,
    int M, int N, int K, size_t sA, size_t sB, size_t sC)
{
    __shared__ float As[8][132];
    __shared__ float Ws[8][132];
    const float* A = Ab + blockIdx.z * sA;
    const float* Bm = Bb + blockIdx.z * sB;
    float* C = Cb + blockIdx.z * sC;
    int tid = threadIdx.x;
    int m0 = blockIdx.y * 128, n0 = blockIdx.x * 128;
    int lrow = tid >> 1;
    int lk = (tid & 1) * 4;
    int bk = tid >> 5;            // 0..7
    int bn = (tid & 31) * 4;      // 0..124
    int tm = (tid >> 4) * 8;
    int tn = (tid & 15) * 8;

    float acc[8][8];
#pragma unroll
    for (int i = 0; i < 8; i++)
#pragma unroll
        for (int j = 0; j < 8; j++) acc[i][j] = 0.f;

    for (int kt = 0; kt < K; kt += 8) {
        float4 av = *reinterpret_cast<const float4*>(A + (size_t)(m0 + lrow) * K + kt + lk);
        float4 bv = *reinterpret_cast<const float4*>(Bm + (size_t)(kt + bk) * N + n0 + bn);
        __syncthreads();
        As[lk+0][lrow] = av.x; As[lk+1][lrow] = av.y; As[lk+2][lrow] = av.z; As[lk+3][lrow] = av.w;
        *reinterpret_cast<float4*>(&Ws[bk][bn]) = bv;
        __syncthreads();
#pragma unroll
        for (int k = 0; k < 8; k++) {
            float a[8], b[8];
            *reinterpret_cast<float4*>(&a[0]) = *reinterpret_cast<float4*>(&As[k][tm]);
            *reinterpret_cast<float4*>(&a[4]) = *reinterpret_cast<float4*>(&As[k][tm+4]);
            *reinterpret_cast<float4*>(&b[0]) = *reinterpret_cast<float4*>(&Ws[k][tn]);
            *reinterpret_cast<float4*>(&b[4]) = *reinterpret_cast<float4*>(&Ws[k][tn+4]);
#pragma unroll
            for (int i = 0; i < 8; i++)
#pragma unroll
                for (int j = 0; j < 8; j++) acc[i][j] += a[i] * b[j];
        }
    }
#pragma unroll
    for (int i = 0; i < 8; i++) {
        float* crow = C + (size_t)(m0 + tm + i) * N + n0 + tn;
#pragma unroll
        for (int j4 = 0; j4 < 2; j4++) {
            float4 v;
            v.x = acc[i][j4*4+0]; v.y = acc[i][j4*4+1];
            v.z = acc[i][j4*4+2]; v.w = acc[i][j4*4+3];
            *reinterpret_cast<float4*>(&crow[j4*4]) = v;
        }
    }
}

// ---------------- encoder LSTM: persistent, 128 CTAs (1/SM), Whh in registers ----------------
// CTA owns 4 hidden indices -> 16 gate rows. Lane layout: lr = lane&15 (gate row),
// ks = warp*2 + (lane>>4) in [0,16) (k-slice of 32). One global barrier per step.
__global__ __launch_bounds__(256) void enc_lstm_kernel(
    const float* __restrict__ xg, const float* __restrict__ Whh)
{
    __shared__ float h_s[BB][HH];        // 16 KB
    __shared__ float red[16][16][9];     // [ks][lr][b] padded
    __shared__ float c_s[BB][4];
    int tid = threadIdx.x;
    int cid = blockIdx.x;
    int lane = tid & 31, warp = tid >> 5;
    int lr = lane & 15;
    int ks = warp * 2 + (lane >> 4);
    int q = lr >> 2, jj = lr & 3;
    int rg = q * HH + cid * 4 + jj;      // global gate row
    int k0 = ks * 32;

    // Whh slice -> registers (loaded ONCE)
    float w[32];
#pragma unroll
    for (int i = 0; i < 32; i += 4) {
        float4 t4 = *reinterpret_cast<const float4*>(&Whh[(size_t)rg * HH + k0 + i]);
        w[i] = t4.x; w[i+1] = t4.y; w[i+2] = t4.z; w[i+3] = t4.w;
    }
    for (int i = tid; i < BB * HH; i += 256) (&h_s[0][0])[i] = 0.f;
    if (tid < 32) c_s[tid >> 2][tid & 3] = 0.f;
    __syncthreads();

    for (int t = 0; t < TT; t++) {
        // prefetch this step's xg early (latency hidden behind the FMA phase)
        float xgv[4];
        if (tid < 32) {
            int b = tid >> 2, j2 = tid & 3;
#pragma unroll
            for (int qq = 0; qq < 4; qq++)
                xgv[qq] = __ldg(&xg[((size_t)(b*TT + t))*G4H + qq*HH + cid*4 + j2]);
        }

        float acc[8];
#pragma unroll
        for (int b = 0; b < 8; b++) acc[b] = 0.f;
#pragma unroll
        for (int i4 = 0; i4 < 8; i4++) {
            float w0 = w[i4*4+0], w1 = w[i4*4+1], w2 = w[i4*4+2], w3 = w[i4*4+3];
#pragma unroll
            for (int b = 0; b < 8; b++) {
                float4 hv = *reinterpret_cast<const float4*>(&h_s[b][k0 + i4*4]);
                acc[b] += w0*hv.x + w1*hv.y + w2*hv.z + w3*hv.w;
            }
        }
#pragma unroll
        for (int b = 0; b < 8; b++) red[ks][lr][b] = acc[b];
        __syncthreads();

        if (tid < 32) {
            int b = tid >> 2, j2 = tid & 3;
            float gate[4];
#pragma unroll
            for (int qq = 0; qq < 4; qq++) {
                float s = xgv[qq];
#pragma unroll
                for (int kk = 0; kk < 16; kk++) s += red[kk][qq*4 + j2][b];
                gate[qq] = s;
            }
            float ii = sigmoidf_(gate[0]);
            float ff = sigmoidf_(gate[1]);
            float gg = tanhf(gate[2]);
            float oo = sigmoidf_(gate[3]);
            float c = ff * c_s[b][j2] + ii * gg;
            float h = oo * tanhf(c);
            c_s[b][j2] = c;
            int hidx = cid*4 + j2;
            d_hglob[b*HH + hidx] = h;
            d_henc[((size_t)(b*TT + t))*HH + hidx] = h;
            __threadfence();   // writes visible GPU-wide before barrier arrive
        }
        __syncthreads();
        if (tid == 0) {
            unsigned int gen = atomicAdd(&d_bar_gen, 0u);
            unsigned int tk = atomicAdd(&d_bar_count, 1u);
            if (tk == ENC_CTAS - 1) {
                atomicExch(&d_bar_count, 0u);
                __threadfence();
                atomicAdd(&d_bar_gen, 1u);
            } else {
                while (atomicAdd(&d_bar_gen, 0u) == gen) { __nanosleep(40); }
            }
            __threadfence();   // acquire: order h reloads after barrier
        }
        __syncthreads();
        // reload full h (L1-bypassing loads: written by other SMs this step)
#pragma unroll
        for (int v = 0; v < 4; v++) {
            int idx = (v * 256 + tid) * 4;
            float4 hv = __ldcg(reinterpret_cast<const float4*>(&d_hglob[idx]));
            *reinterpret_cast<float4*>(&(&h_s[0][0])[idx]) = hv;
        }
        __syncthreads();
    }
}

// ---------------- pos LSTM + mu/sigma heads + mu scan (single CTA) ----------------
__global__ void pos_kernel(const int* __restrict__ pad_len,
                           const float* __restrict__ Whh,
                           const float* __restrict__ Wmu, const float* __restrict__ bmu,
                           const float* __restrict__ Wsig, const float* __restrict__ bsig)
{
    __shared__ float Whh_s[G4P][PP];
    __shared__ float Wmu_s[3][PP];
    __shared__ float Wsig_s[PP];
    __shared__ float hp[BB][PP], cp[BB][PP], gate_s[BB][G4P];
    __shared__ float mu_prev[BB];
    int tid = threadIdx.x;
    for (int i = tid; i < G4P*PP; i += blockDim.x) Whh_s[i/PP][i%PP] = Whh[i];
    for (int i = tid; i < 3*PP;  i += blockDim.x) Wmu_s[i/PP][i%PP] = Wmu[i];
    if (tid < PP) Wsig_s[tid] = Wsig[tid];
    for (int i = tid; i < BB*PP; i += blockDim.x) { hp[i/PP][i%PP] = 0.f; cp[i/PP][i%PP] = 0.f; }
    if (tid < BB) mu_prev[tid] = 0.f;
    __syncthreads();

    for (int t = 0; t < TT; t++) {
        if (tid < BB * G4P) {
            int b = tid / G4P, r = tid % G4P;
            float acc = d_xg_pos[((size_t)(b*TT + t))*G4P + r];
#pragma unroll
            for (int k = 0; k < PP; k++) acc += Whh_s[r][k] * hp[b][k];
            gate_s[b][r] = acc;
        }
        __syncthreads();
        if (tid < BB * PP) {
            int b = tid / PP, j = tid % PP;
            float ii = sigmoidf_(gate_s[b][j]);
            float ff = sigmoidf_(gate_s[b][PP + j]);
            float gg = tanhf(gate_s[b][2*PP + j]);
            float oo = sigmoidf_(gate_s[b][3*PP + j]);
            float c = ff * cp[b][j] + ii * gg;
            cp[b][j] = c;
            hp[b][j] = oo * tanhf(c);
        }
        __syncthreads();
        if (tid < BB) {
            int b = tid;
            float L = (float)pad_len[b];
            float m3[3];
#pragma unroll
            for (int g = 0; g < 3; g++) {
                float s = bmu[g];
#pragma unroll
                for (int p = 0; p < PP; p++) s += hp[b][p] * Wmu_s[g][p];
                m3[g] = fmaxf(s, 0.f);
            }
            float ss = bsig[0];
#pragma unroll
            for (int p = 0; p < PP; p++) ss += hp[b][p] * Wsig_s[p];
            float sgv = sigmoidf_(ss);
            float mu = m3[0]*mu_prev[b] + m3[1]/L + m3[2]*((float)(t+1))/L;
            mu = fmaxf(mu, (float)t / L);
            mu_prev[b] = mu;
            d_mu[b*TT + t] = mu;
            d_sg[b*TT + t] = sgv;
        }
        __syncthreads();
    }
}

// ---------------- normalized Gaussian prefix weights: one warp per (b, tq) ----------------
__global__ void attn_kernel(const int* __restrict__ pad_len) {
    int wq = blockIdx.x * 8 + (threadIdx.x >> 5);
    int lane = threadIdx.x & 31;
    int b = wq >> 9, tq = wq & 511;
    float L = (float)pad_len[b];
    float mu = d_mu[b*TT + tq], sg = d_sg[b*TT + tq];
    float denom = 2.f * sg * sg + 0.001f;
    float* grow = &d_gw[((size_t)(b*TT + tq)) * TT];
    float wv[16];
    float sum = 0.f;
#pragma unroll
    for (int i = 0; i < 16; i++) {
        int tk = lane + i*32;
        float dd = (float)tk / L - mu;
        float v = (tk <= tq) ? __expf(-dd*dd / denom) : 0.f;
        wv[i] = v; sum += v;
    }
#pragma unroll
    for (int o = 16; o; o >>= 1) sum += __shfl_xor_sync(0xffffffffu, sum, o);
    float inv = 1.f / fmaxf(sum, 1e-12f);
#pragma unroll
    for (int i = 0; i < 16; i++) grow[lane + i*32] = wv[i] * inv;
}

// ---------------- concat [ctx, enc] ----------------
__global__ void concat_kernel() {
    int idx = blockIdx.x * blockDim.x + threadIdx.x;     // float4 index per half
    if (idx >= MTOK * 128) return;
    int m = idx >> 7, h4 = idx & 127;
    float4 c4 = *reinterpret_cast<const float4*>(&d_ctx[((size_t)m << 9) + (h4 << 2)]);
    float4 e4 = *reinterpret_cast<const float4*>(&d_henc[((size_t)m << 9) + (h4 << 2)]);
    *reinterpret_cast<float4*>(&d_cat[(size_t)m*1024 + (h4 << 2)]) = c4;
    *reinterpret_cast<float4*>(&d_cat[(size_t)m*1024 + 512 + (h4 << 2)]) = e4;
}

// ---------------- launcher ----------------
extern "C" void kernel_launch(void* const* d_in, const int* in_sizes, int n_in,
                              void* d_out, int out_size)
{
    const int*   tokens   = (const int*)d_in[0];
    const int*   pad_len  = (const int*)d_in[1];
    const float* embedding= (const float*)d_in[2];
    const float* enc_Wih  = (const float*)d_in[3];
    const float* enc_Whh  = (const float*)d_in[4];
    const float* enc_bih  = (const float*)d_in[5];
    const float* enc_bhh  = (const float*)d_in[6];
    const float* pos_Wih  = (const float*)d_in[7];
    const float* pos_Whh  = (const float*)d_in[8];
    const float* pos_bih  = (const float*)d_in[9];
    const float* pos_bhh  = (const float*)d_in[10];
    const float* W_mu     = (const float*)d_in[11];
    const float* b_mu     = (const float*)d_in[12];
    const float* W_sig    = (const float*)d_in[13];
    const float* b_sig    = (const float*)d_in[14];
    const float* W_cat    = (const float*)d_in[15];
    const float* b_cat    = (const float*)d_in[16];
    const float* dec_b    = (const float*)d_in[17];
    float* out = (float*)d_out;

    float *p_emb, *p_xg_enc, *p_henc, *p_xg_pos, *p_gw, *p_ctx, *p_cat, *p_comb;
    cudaGetSymbolAddress((void**)&p_emb,    d_emb);
    cudaGetSymbolAddress((void**)&p_xg_enc, d_xg_enc);
    cudaGetSymbolAddress((void**)&p_henc,   d_henc);
    cudaGetSymbolAddress((void**)&p_xg_pos, d_xg_pos);
    cudaGetSymbolAddress((void**)&p_gw,     d_gw);
    cudaGetSymbolAddress((void**)&p_ctx,    d_ctx);
    cudaGetSymbolAddress((void**)&p_cat,    d_cat);
    cudaGetSymbolAddress((void**)&p_comb,   d_comb);

    // 1) gather embeddings
    gather_kernel<<<MTOK, 128>>>(tokens, embedding);
    // 2) xg_enc = emb @ enc_Wih^T + bih + bhh   [4096,2048]
    gemm_nt_kernel<0,false><<<dim3(G4H/128, MTOK/128), 256>>>(
        p_emb, enc_Wih, enc_bih, enc_bhh, p_xg_enc, MTOK, G4H, HH);
    // 3) encoder LSTM (persistent, one launch, Whh register-resident)
    enc_lstm_kernel<<<ENC_CTAS, 256>>>(p_xg_enc, enc_Whh);
    // 4) xg_pos = henc @ pos_Wih^T + biases   [4096,80]
    gemm_nt_kernel<0,true><<<dim3(1, MTOK/128), 256>>>(
        p_henc, pos_Wih, pos_bih, pos_bhh, p_xg_pos, MTOK, G4P, HH);
    // 5) pos LSTM + heads + mu scan
    pos_kernel<<<1, 640>>>(pad_len, pos_Whh, W_mu, b_mu, W_sig, b_sig);
    // 6) attention weights (normalized)
    attn_kernel<<<(BB*TT)/8, 256>>>(pad_len);
    // 7) ctx = g @ enc (batched over b)
    gemm_nn_kernel<<<dim3(HH/128, TT/128, BB), 256>>>(
        p_gw, p_henc, p_ctx, TT, HH, TT,
        (size_t)TT*TT, (size_t)TT*HH, (size_t)TT*HH);
    // 8) concat
    concat_kernel<<<(MTOK*128)/256, 256>>>();
    // 9) comb = tanh(cat @ W_cat^T + b_cat)
    gemm_nt_kernel<1,false><<<dim3(HH/128, MTOK/128), 256>>>(
        p_cat, W_cat, b_cat, nullptr, p_comb, MTOK, HH, 2*HH);
    // 10) logits = comb @ embedding^T + dec_b  -> d_out
    gemm_nt_kernel<0,false><<<dim3(VV/128, MTOK/128), 256>>>(
        p_comb, embedding, dec_b, nullptr, out, MTOK, VV, HH);

    (void)in_sizes; (void)n_in; (void)out_size;
}

// round 9
// speedup vs baseline: 1.3201x; 1.2980x over previous
#include <cuda_runtime.h>
#include <cuda_bf16.h>
#include <cstdint>
#include <cstddef>

#define BB 8
#define TT 512
#define HH 512
#define VV 32000
#define PP 20
#define G4H 2048
#define G4P 80
#define MTOK (BB*TT)   // 4096
#define KD 1536        // decoder split-K: [hi | hi | lo]

// ---------------- scratch (static device globals; no allocations anywhere) ----------------
__device__ float d_emb[MTOK*HH];
__device__ float d_xg_enc[MTOK*G4H];
__device__ float d_henc[MTOK*HH];
__device__ float d_hglob[BB*HH];
__device__ float d_cstate[BB*HH];
__device__ float d_xg_pos[MTOK*G4P];
__device__ float d_mu[BB*TT];
__device__ float d_sg[BB*TT];
__device__ float d_gw[(size_t)BB*TT*TT];
__device__ float d_ctx[MTOK*HH];
__device__ float d_cat[MTOK*2*HH];
__device__ float d_comb[MTOK*HH];
__device__ __nv_bfloat16 d_A2[(size_t)MTOK*KD];   // comb split   [4096,1536]
__device__ __nv_bfloat16 d_B2[(size_t)VV*KD];     // emb split    [32000,1536]

__device__ __forceinline__ float sigmoidf_(float x) { return 1.f / (1.f + __expf(-x)); }

// ---------------- embedding gather ----------------
__global__ void gather_kernel(const int* __restrict__ tokens, const float* __restrict__ emb) {
    int m = blockIdx.x;
    int tok = tokens[m];
    const float4* src = reinterpret_cast<const float4*>(emb + (size_t)tok * HH);
    float4* dst = reinterpret_cast<float4*>(d_emb + (size_t)m * HH);
    dst[threadIdx.x] = src[threadIdx.x];
}

// ---------------- generic fp32 SGEMM: C = act(A[M,K] @ W[N,K]^T + b1 + b2) ----------------
template<int ACT, bool GUARD>
__global__ __launch_bounds__(256) void gemm_nt_kernel(
    const float* __restrict__ A, const float* __restrict__ W,
    const float* __restrict__ b1, const float* __restrict__ b2,
    float* __restrict__ C, int M, int N, int K)
{
    __shared__ float As[8][132];
    __shared__ float Ws[8][132];
    int tid = threadIdx.x;
    int m0 = blockIdx.y * 128, n0 = blockIdx.x * 128;
    int lrow = tid >> 1;
    int lk = (tid & 1) * 4;
    bool a_ok = !GUARD || (m0 + lrow) < M;
    bool w_ok = !GUARD || (n0 + lrow) < N;
    const float* Aptr = A + (size_t)(m0 + lrow) * K + lk;
    const float* Wptr = W + (size_t)(n0 + lrow) * K + lk;
    int tm = (tid >> 4) * 8;
    int tn = (tid & 15) * 8;

    float acc[8][8];
#pragma unroll
    for (int i = 0; i < 8; i++)
#pragma unroll
        for (int j = 0; j < 8; j++) acc[i][j] = 0.f;

    for (int kt = 0; kt < K; kt += 8) {
        float4 av = a_ok ? *reinterpret_cast<const float4*>(Aptr + kt) : make_float4(0,0,0,0);
        float4 wv = w_ok ? *reinterpret_cast<const float4*>(Wptr + kt) : make_float4(0,0,0,0);
        __syncthreads();
        As[lk+0][lrow] = av.x; As[lk+1][lrow] = av.y; As[lk+2][lrow] = av.z; As[lk+3][lrow] = av.w;
        Ws[lk+0][lrow] = wv.x; Ws[lk+1][lrow] = wv.y; Ws[lk+2][lrow] = wv.z; Ws[lk+3][lrow] = wv.w;
        __syncthreads();
#pragma unroll
        for (int k = 0; k < 8; k++) {
            float a[8], b[8];
            *reinterpret_cast<float4*>(&a[0]) = *reinterpret_cast<float4*>(&As[k][tm]);
            *reinterpret_cast<float4*>(&a[4]) = *reinterpret_cast<float4*>(&As[k][tm+4]);
            *reinterpret_cast<float4*>(&b[0]) = *reinterpret_cast<float4*>(&Ws[k][tn]);
            *reinterpret_cast<float4*>(&b[4]) = *reinterpret_cast<float4*>(&Ws[k][tn+4]);
#pragma unroll
            for (int i = 0; i < 8; i++)
#pragma unroll
                for (int j = 0; j < 8; j++) acc[i][j] += a[i] * b[j];
        }
    }

    float bias[8];
#pragma unroll
    for (int j = 0; j < 8; j++) {
        int gn = n0 + tn + j;
        float bv = 0.f;
        if (!GUARD || gn < N) {
            if (b1) bv += b1[gn];
            if (b2) bv += b2[gn];
        }
        bias[j] = bv;
    }

    if (!GUARD) {
#pragma unroll
        for (int i = 0; i < 8; i++) {
            float* crow = C + (size_t)(m0 + tm + i) * N + n0 + tn;
#pragma unroll
            for (int j4 = 0; j4 < 2; j4++) {
                float4 v;
                float v0 = acc[i][j4*4+0] + bias[j4*4+0];
                float v1 = acc[i][j4*4+1] + bias[j4*4+1];
                float v2 = acc[i][j4*4+2] + bias[j4*4+2];
                float v3 = acc[i][j4*4+3] + bias[j4*4+3];
                if (ACT == 1) { v0 = tanhf(v0); v1 = tanhf(v1); v2 = tanhf(v2); v3 = tanhf(v3); }
                v.x = v0; v.y = v1; v.z = v2; v.w = v3;
                *reinterpret_cast<float4*>(&crow[j4*4]) = v;
            }
        }
    } else {
#pragma unroll
        for (int i = 0; i < 8; i++) {
            int gm = m0 + tm + i;
            if (gm >= M) continue;
#pragma unroll
            for (int j = 0; j < 8; j++) {
                int gn = n0 + tn + j;
                if (gn >= N) continue;
                float v = acc[i][j] + bias[j];
                if (ACT == 1) v = tanhf(v);
                C[(size_t)gm * N + gn] = v;
            }
        }
    }
}

// ---------------- batched fp32 SGEMM: C[z] = A[z] @ B[z], B row-major [K,N] ----------------
__global__ __launch_bounds__(256) void gemm_nn_kernel(
    const float* __restrict__ Ab, const float* __restrict__ Bb, float* __restrict__ Cb,
    int M, int N, int K, size_t sA, size_t sB, size_t sC)
{
    __shared__ float As[8][132];
    __shared__ float Ws[8][132];
    const float* A = Ab + blockIdx.z * sA;
    const float* Bm = Bb + blockIdx.z * sB;
    float* C = Cb + blockIdx.z * sC;
    int tid = threadIdx.x;
    int m0 = blockIdx.y * 128, n0 = blockIdx.x * 128;
    int lrow = tid >> 1;
    int lk = (tid & 1) * 4;
    int bk = tid >> 5;
    int bn = (tid & 31) * 4;
    int tm = (tid >> 4) * 8;
    int tn = (tid & 15) * 8;

    float acc[8][8];
#pragma unroll
    for (int i = 0; i < 8; i++)
#pragma unroll
        for (int j = 0; j < 8; j++) acc[i][j] = 0.f;

    for (int kt = 0; kt < K; kt += 8) {
        float4 av = *reinterpret_cast<const float4*>(A + (size_t)(m0 + lrow) * K + kt + lk);
        float4 bv = *reinterpret_cast<const float4*>(Bm + (size_t)(kt + bk) * N + n0 + bn);
        __syncthreads();
        As[lk+0][lrow] = av.x; As[lk+1][lrow] = av.y; As[lk+2][lrow] = av.z; As[lk+3][lrow] = av.w;
        *reinterpret_cast<float4*>(&Ws[bk][bn]) = bv;
        __syncthreads();
#pragma unroll
        for (int k = 0; k < 8; k++) {
            float a[8], b[8];
            *reinterpret_cast<float4*>(&a[0]) = *reinterpret_cast<float4*>(&As[k][tm]);
            *reinterpret_cast<float4*>(&a[4]) = *reinterpret_cast<float4*>(&As[k][tm+4]);
            *reinterpret_cast<float4*>(&b[0]) = *reinterpret_cast<float4*>(&Ws[k][tn]);
            *reinterpret_cast<float4*>(&b[4]) = *reinterpret_cast<float4*>(&Ws[k][tn+4]);
#pragma unroll
            for (int i = 0; i < 8; i++)
#pragma unroll
                for (int j = 0; j < 8; j++) acc[i][j] += a[i] * b[j];
        }
    }
#pragma unroll
    for (int i = 0; i < 8; i++) {
        float* crow = C + (size_t)(m0 + tm + i) * N + n0 + tn;
#pragma unroll
        for (int j4 = 0; j4 < 2; j4++) {
            float4 v;
            v.x = acc[i][j4*4+0]; v.y = acc[i][j4*4+1];
            v.z = acc[i][j4*4+2]; v.w = acc[i][j4*4+3];
            *reinterpret_cast<float4*>(&crow[j4*4]) = v;
        }
    }
}

// ---------------- encoder LSTM: one launch per timestep (proven; cannot hang) ----------------
__global__ void enc_init_kernel() {
    int i = blockIdx.x * blockDim.x + threadIdx.x;
    if (i < BB * HH) { d_hglob[i] = 0.f; d_cstate[i] = 0.f; }
}

__global__ __launch_bounds__(256) void enc_step_kernel(
    int t, const float* __restrict__ xg, const float* __restrict__ Whh)
{
    __shared__ float h_s[BB * HH];
    __shared__ float red_s[16][8];
    int tid = threadIdx.x, cid = blockIdx.x;
    int lane = tid & 31, w = tid >> 5;

#pragma unroll
    for (int i = 0; i < 4; i++) {
        int idx = i * 256 + tid;
        reinterpret_cast<float4*>(h_s)[idx] = reinterpret_cast<const float4*>(d_hglob)[idx];
    }
    __syncthreads();

    int rl0 = w * 2, rl1 = w * 2 + 1;
    const float* wrow0 = Whh + (size_t)((rl0 >> 2) * HH + cid * 4 + (rl0 & 3)) * HH;
    const float* wrow1 = Whh + (size_t)((rl1 >> 2) * HH + cid * 4 + (rl1 & 3)) * HH;

    float acc0[8], acc1[8];
#pragma unroll
    for (int b = 0; b < 8; b++) { acc0[b] = 0.f; acc1[b] = 0.f; }

#pragma unroll
    for (int it = 0; it < 4; it++) {
        int k0 = it * 128 + lane * 4;
        float4 w0 = *reinterpret_cast<const float4*>(wrow0 + k0);
        float4 w1 = *reinterpret_cast<const float4*>(wrow1 + k0);
#pragma unroll
        for (int b = 0; b < 8; b++) {
            float4 hv = *reinterpret_cast<const float4*>(&h_s[b * HH + k0]);
            acc0[b] += w0.x*hv.x + w0.y*hv.y + w0.z*hv.z + w0.w*hv.w;
            acc1[b] += w1.x*hv.x + w1.y*hv.y + w1.z*hv.z + w1.w*hv.w;
        }
    }
#pragma unroll
    for (int b = 0; b < 8; b++) {
        float v0 = acc0[b], v1 = acc1[b];
#pragma unroll
        for (int o = 16; o; o >>= 1) {
            v0 += __shfl_xor_sync(0xffffffffu, v0, o);
            v1 += __shfl_xor_sync(0xffffffffu, v1, o);
        }
        if (lane == 0) { red_s[rl0][b] = v0; red_s[rl1][b] = v1; }
    }
    __syncthreads();

    if (tid < 32) {
        int b = tid >> 2, j2 = tid & 3;
        float g4[4];
#pragma unroll
        for (int q = 0; q < 4; q++)
            g4[q] = xg[((size_t)(b*TT + t))*G4H + q*HH + cid*4 + j2] + red_s[q*4 + j2][b];
        float ii = sigmoidf_(g4[0]);
        float ff = sigmoidf_(g4[1]);
        float gg = tanhf(g4[2]);
        float oo = sigmoidf_(g4[3]);
        int hidx = cid*4 + j2;
        float c = ff * d_cstate[b*HH + hidx] + ii * gg;
        float h = oo * tanhf(c);
        d_cstate[b*HH + hidx] = c;
        d_hglob[b*HH + hidx]  = h;
        d_henc[((size_t)(b*TT + t))*HH + hidx] = h;
    }
}

// ---------------- pos LSTM + mu/sigma heads + mu scan (single CTA) ----------------
__global__ void pos_kernel(const int* __restrict__ pad_len,
                           const float* __restrict__ Whh,
                           const float* __restrict__ Wmu, const float* __restrict__ bmu,
                           const float* __restrict__ Wsig, const float* __restrict__ bsig)
{
    __shared__ float Whh_s[G4P][PP];
    __shared__ float Wmu_s[3][PP];
    __shared__ float Wsig_s[PP];
    __shared__ float hp[BB][PP], cp[BB][PP], gate_s[BB][G4P];
    __shared__ float mu_prev[BB];
    int tid = threadIdx.x;
    for (int i = tid; i < G4P*PP; i += blockDim.x) Whh_s[i/PP][i%PP] = Whh[i];
    for (int i = tid; i < 3*PP;  i += blockDim.x) Wmu_s[i/PP][i%PP] = Wmu[i];
    if (tid < PP) Wsig_s[tid] = Wsig[tid];
    for (int i = tid; i < BB*PP; i += blockDim.x) { hp[i/PP][i%PP] = 0.f; cp[i/PP][i%PP] = 0.f; }
    if (tid < BB) mu_prev[tid] = 0.f;
    __syncthreads();

    for (int t = 0; t < TT; t++) {
        if (tid < BB * G4P) {
            int b = tid / G4P, r = tid % G4P;
            float acc = d_xg_pos[((size_t)(b*TT + t))*G4P + r];
#pragma unroll
            for (int k = 0; k < PP; k++) acc += Whh_s[r][k] * hp[b][k];
            gate_s[b][r] = acc;
        }
        __syncthreads();
        if (tid < BB * PP) {
            int b = tid / PP, j = tid % PP;
            float ii = sigmoidf_(gate_s[b][j]);
            float ff = sigmoidf_(gate_s[b][PP + j]);
            float gg = tanhf(gate_s[b][2*PP + j]);
            float oo = sigmoidf_(gate_s[b][3*PP + j]);
            float c = ff * cp[b][j] + ii * gg;
            cp[b][j] = c;
            hp[b][j] = oo * tanhf(c);
        }
        __syncthreads();
        if (tid < BB) {
            int b = tid;
            float L = (float)pad_len[b];
            float m3[3];
#pragma unroll
            for (int g = 0; g < 3; g++) {
                float s = bmu[g];
#pragma unroll
                for (int p = 0; p < PP; p++) s += hp[b][p] * Wmu_s[g][p];
                m3[g] = fmaxf(s, 0.f);
            }
            float ss = bsig[0];
#pragma unroll
            for (int p = 0; p < PP; p++) ss += hp[b][p] * Wsig_s[p];
            float sgv = sigmoidf_(ss);
            float mu = m3[0]*mu_prev[b] + m3[1]/L + m3[2]*((float)(t+1))/L;
            mu = fmaxf(mu, (float)t / L);
            mu_prev[b] = mu;
            d_mu[b*TT + t] = mu;
            d_sg[b*TT + t] = sgv;
        }
        __syncthreads();
    }
}

// ---------------- normalized Gaussian prefix weights ----------------
__global__ void attn_kernel(const int* __restrict__ pad_len) {
    int wq = blockIdx.x * 8 + (threadIdx.x >> 5);
    int lane = threadIdx.x & 31;
    int b = wq >> 9, tq = wq & 511;
    float L = (float)pad_len[b];
    float mu = d_mu[b*TT + tq], sg = d_sg[b*TT + tq];
    float denom = 2.f * sg * sg + 0.001f;
    float* grow = &d_gw[((size_t)(b*TT + tq)) * TT];
    float wv[16];
    float sum = 0.f;
#pragma unroll
    for (int i = 0; i < 16; i++) {
        int tk = lane + i*32;
        float dd = (float)tk / L - mu;
        float v = (tk <= tq) ? __expf(-dd*dd / denom) : 0.f;
        wv[i] = v; sum += v;
    }
#pragma unroll
    for (int o = 16; o; o >>= 1) sum += __shfl_xor_sync(0xffffffffu, sum, o);
    float inv = 1.f / fmaxf(sum, 1e-12f);
#pragma unroll
    for (int i = 0; i < 16; i++) grow[lane + i*32] = wv[i] * inv;
}

// ---------------- concat [ctx, enc] ----------------
__global__ void concat_kernel() {
    int idx = blockIdx.x * blockDim.x + threadIdx.x;
    if (idx >= MTOK * 128) return;
    int m = idx >> 7, h4 = idx & 127;
    float4 c4 = *reinterpret_cast<const float4*>(&d_ctx[((size_t)m << 9) + (h4 << 2)]);
    float4 e4 = *reinterpret_cast<const float4*>(&d_henc[((size_t)m << 9) + (h4 << 2)]);
    *reinterpret_cast<float4*>(&d_cat[(size_t)m*1024 + (h4 << 2)]) = c4;
    *reinterpret_cast<float4*>(&d_cat[(size_t)m*1024 + 512 + (h4 << 2)]) = e4;
}

// ---------------- fp32 -> split-bf16 converts ----------------
// A2 layout: [0,512)=hi, [512,1024)=hi, [1024,1536)=lo
// B2 layout: [0,512)=hi, [512,1024)=lo, [1024,1536)=hi
__device__ __forceinline__ void split_bf16(float a, unsigned short& h, unsigned short& l) {
    __nv_bfloat16 hb = __float2bfloat16_rn(a);
    float lo = a - __bfloat162float(hb);
    __nv_bfloat16 lb = __float2bfloat16_rn(lo);
    h = *reinterpret_cast<unsigned short*>(&hb);
    l = *reinterpret_cast<unsigned short*>(&lb);
}

__global__ void convA_kernel() {   // comb [4096,512] -> d_A2
    int i = blockIdx.x * 256 + threadIdx.x;         // float4 id, 4096*128 total
    int m = i >> 7, k4 = (i & 127) * 4;
    float4 v = *reinterpret_cast<const float4*>(&d_comb[(size_t)m*HH + k4]);
    unsigned short h[4], l[4];
    split_bf16(v.x, h[0], l[0]); split_bf16(v.y, h[1], l[1]);
    split_bf16(v.z, h[2], l[2]); split_bf16(v.w, h[3], l[3]);
    ushort4 H = make_ushort4(h[0], h[1], h[2], h[3]);
    ushort4 Lo = make_ushort4(l[0], l[1], l[2], l[3]);
    __nv_bfloat16* base = d_A2 + (size_t)m * KD + k4;
    *reinterpret_cast<ushort4*>(base)        = H;
    *reinterpret_cast<ushort4*>(base + 512)  = H;
    *reinterpret_cast<ushort4*>(base + 1024) = Lo;
}

__global__ void convB_kernel(const float* __restrict__ emb) {  // emb [32000,512] -> d_B2
    int i = blockIdx.x * 256 + threadIdx.x;         // float4 id, 32000*128 total
    int n = i >> 7, k4 = (i & 127) * 4;
    float4 v = *reinterpret_cast<const float4*>(&emb[(size_t)n*HH + k4]);
    unsigned short h[4], l[4];
    split_bf16(v.x, h[0], l[0]); split_bf16(v.y, h[1], l[1]);
    split_bf16(v.z, h[2], l[2]); split_bf16(v.w, h[3], l[3]);
    ushort4 H = make_ushort4(h[0], h[1], h[2], h[3]);
    ushort4 Lo = make_ushort4(l[0], l[1], l[2], l[3]);
    __nv_bfloat16* base = d_B2 + (size_t)n * KD + k4;
    *reinterpret_cast<ushort4*>(base)        = H;
    *reinterpret_cast<ushort4*>(base + 512)  = Lo;
    *reinterpret_cast<ushort4*>(base + 1024) = H;
}

// ---------------- decoder: bf16 NT GEMM via mma.sync, fp32 accum ----------------
__device__ __forceinline__ void ldsm_x4(uint32_t& r0, uint32_t& r1, uint32_t& r2, uint32_t& r3,
                                        uint32_t addr) {
    asm volatile("ldmatrix.sync.aligned.m8n8.x4.shared.b16 {%0,%1,%2,%3}, [%4];"
                 : "=r"(r0), "=r"(r1), "=r"(r2), "=r"(r3) : "r"(addr));
}
__device__ __forceinline__ void ldsm_x2(uint32_t& r0, uint32_t& r1, uint32_t addr) {
    asm volatile("ldmatrix.sync.aligned.m8n8.x2.shared.b16 {%0,%1}, [%2];"
                 : "=r"(r0), "=r"(r1) : "r"(addr));
}
__device__ __forceinline__ void mma_bf16(float* c, const uint32_t* a, const uint32_t* b) {
    asm volatile(
        "mma.sync.aligned.m16n8k16.row.col.f32.bf16.bf16.f32 "
        "{%0,%1,%2,%3}, {%4,%5,%6,%7}, {%8,%9}, {%0,%1,%2,%3};"
        : "+f"(c[0]), "+f"(c[1]), "+f"(c[2]), "+f"(c[3])
        : "r"(a[0]), "r"(a[1]), "r"(a[2]), "r"(a[3]), "r"(b[0]), "r"(b[1]));
}

// BM=BN=128, BK=32, 256 threads (8 warps, 2x4), warp tile 64x32, K=1536 (48 iters).
// grid (32 m-tiles, 250 n-tiles) — m fast so a wave shares B tiles.
__global__ __launch_bounds__(256) void dec_mma_kernel(
    const __nv_bfloat16* __restrict__ A, const __nv_bfloat16* __restrict__ B,
    const float* __restrict__ bias, float* __restrict__ C)
{
    __shared__ __align__(16) __nv_bfloat16 As[2][128][40];
    __shared__ __align__(16) __nv_bfloat16 Bs[2][128][40];
    int tid = threadIdx.x, lane = tid & 31, w = tid >> 5;
    int wm = w >> 2, wn = w & 3;
    int m0 = blockIdx.x * 128, n0 = blockIdx.y * 128;

    int lr = tid >> 2;              // 0..63
    int lc = (tid & 3) * 8;         // bf16 col offset {0,8,16,24}
    const __nv_bfloat16* Ag = A + (size_t)(m0 + lr) * KD + lc;
    const __nv_bfloat16* Bg = B + (size_t)(n0 + lr) * KD + lc;

    float acc[4][4][4];
#pragma unroll
    for (int i = 0; i < 4; i++)
#pragma unroll
        for (int j = 0; j < 4; j++) { acc[i][j][0]=0.f; acc[i][j][1]=0.f; acc[i][j][2]=0.f; acc[i][j][3]=0.f; }

    uint4 pa0 = *reinterpret_cast<const uint4*>(Ag);
    uint4 pa1 = *reinterpret_cast<const uint4*>(Ag + (size_t)64 * KD);
    uint4 pb0 = *reinterpret_cast<const uint4*>(Bg);
    uint4 pb1 = *reinterpret_cast<const uint4*>(Bg + (size_t)64 * KD);

    uint32_t sA0 = (uint32_t)__cvta_generic_to_shared(&As[0][0][0]);
    uint32_t sB0 = (uint32_t)__cvta_generic_to_shared(&Bs[0][0][0]);

    for (int kt = 0; kt < 48; kt++) {
        int buf = kt & 1;
        *reinterpret_cast<uint4*>(&As[buf][lr][lc])      = pa0;
        *reinterpret_cast<uint4*>(&As[buf][lr + 64][lc]) = pa1;
        *reinterpret_cast<uint4*>(&Bs[buf][lr][lc])      = pb0;
        *reinterpret_cast<uint4*>(&Bs[buf][lr + 64][lc]) = pb1;
        __syncthreads();
        if (kt < 47) {
            const __nv_bfloat16* Agn = Ag + (kt + 1) * 32;
            const __nv_bfloat16* Bgn = Bg + (kt + 1) * 32;
            pa0 = *reinterpret_cast<const uint4*>(Agn);
            pa1 = *reinterpret_cast<const uint4*>(Agn + (size_t)64 * KD);
            pb0 = *reinterpret_cast<const uint4*>(Bgn);
            pb1 = *reinterpret_cast<const uint4*>(Bgn + (size_t)64 * KD);
        }
        uint32_t sAb = sA0 + (uint32_t)buf * 128 * 40 * 2;
        uint32_t sBb = sB0 + (uint32_t)buf * 128 * 40 * 2;
#pragma unroll
        for (int k16 = 0; k16 < 2; k16++) {
            uint32_t af[4][4], bf[4][2];
#pragma unroll
            for (int mt = 0; mt < 4; mt++) {
                uint32_t addr = sAb + ((wm*64 + mt*16 + (lane & 15)) * 40 + k16*16 + (lane >> 4)*8) * 2;
                ldsm_x4(af[mt][0], af[mt][1], af[mt][2], af[mt][3], addr);
            }
#pragma unroll
            for (int nt = 0; nt < 4; nt++) {
                uint32_t addr = sBb + ((wn*32 + nt*8 + (lane & 7)) * 40 + k16*16 + ((lane >> 3) & 1)*8) * 2;
                ldsm_x2(bf[nt][0], bf[nt][1], addr);
            }
#pragma unroll
            for (int mt = 0; mt < 4; mt++)
#pragma unroll
                for (int nt = 0; nt < 4; nt++)
                    mma_bf16(acc[mt][nt], af[mt], bf[nt]);
        }
        __syncthreads();
    }

    // epilogue: += bias, store fp32
#pragma unroll
    for (int mt = 0; mt < 4; mt++) {
        int r0 = m0 + wm*64 + mt*16 + (lane >> 2);
#pragma unroll
        for (int nt = 0; nt < 4; nt++) {
            int cc = n0 + wn*32 + nt*8 + (lane & 3)*2;
            float b0 = bias[cc], b1 = bias[cc + 1];
            float2 v0 = make_float2(acc[mt][nt][0] + b0, acc[mt][nt][1] + b1);
            float2 v1 = make_float2(acc[mt][nt][2] + b0, acc[mt][nt][3] + b1);
            *reinterpret_cast<float2*>(&C[(size_t)r0 * VV + cc])       = v0;
            *reinterpret_cast<float2*>(&C[(size_t)(r0 + 8) * VV + cc]) = v1;
        }
    }
}

// ---------------- launcher ----------------
extern "C" void kernel_launch(void* const* d_in, const int* in_sizes, int n_in,
                              void* d_out, int out_size)
{
    const int*   tokens   = (const int*)d_in[0];
    const int*   pad_len  = (const int*)d_in[1];
    const float* embedding= (const float*)d_in[2];
    const float* enc_Wih  = (const float*)d_in[3];
    const float* enc_Whh  = (const float*)d_in[4];
    const float* enc_bih  = (const float*)d_in[5];
    const float* enc_bhh  = (const float*)d_in[6];
    const float* pos_Wih  = (const float*)d_in[7];
    const float* pos_Whh  = (const float*)d_in[8];
    const float* pos_bih  = (const float*)d_in[9];
    const float* pos_bhh  = (const float*)d_in[10];
    const float* W_mu     = (const float*)d_in[11];
    const float* b_mu     = (const float*)d_in[12];
    const float* W_sig    = (const float*)d_in[13];
    const float* b_sig    = (const float*)d_in[14];
    const float* W_cat    = (const float*)d_in[15];
    const float* b_cat    = (const float*)d_in[16];
    const float* dec_b    = (const float*)d_in[17];
    float* out = (float*)d_out;

    float *p_emb, *p_xg_enc, *p_henc, *p_xg_pos, *p_gw, *p_ctx, *p_cat, *p_comb;
    __nv_bfloat16 *p_A2, *p_B2;
    cudaGetSymbolAddress((void**)&p_emb,    d_emb);
    cudaGetSymbolAddress((void**)&p_xg_enc, d_xg_enc);
    cudaGetSymbolAddress((void**)&p_henc,   d_henc);
    cudaGetSymbolAddress((void**)&p_xg_pos, d_xg_pos);
    cudaGetSymbolAddress((void**)&p_gw,     d_gw);
    cudaGetSymbolAddress((void**)&p_ctx,    d_ctx);
    cudaGetSymbolAddress((void**)&p_cat,    d_cat);
    cudaGetSymbolAddress((void**)&p_comb,   d_comb);
    cudaGetSymbolAddress((void**)&p_A2,     d_A2);
    cudaGetSymbolAddress((void**)&p_B2,     d_B2);

    // 1) gather embeddings
    gather_kernel<<<MTOK, 128>>>(tokens, embedding);
    // 2) B2 = split-bf16(embedding)   (independent of everything downstream)
    convB_kernel<<<(VV*128)/256, 256>>>(embedding);
    // 3) xg_enc = emb @ enc_Wih^T + biases
    gemm_nt_kernel<0,false><<<dim3(G4H/128, MTOK/128), 256>>>(
        p_emb, enc_Wih, enc_bih, enc_bhh, p_xg_enc, MTOK, G4H, HH);
    // 4) encoder LSTM: init + 512 sequential step launches (proven path)
    enc_init_kernel<<<(BB*HH + 255)/256, 256>>>();
    for (int t = 0; t < TT; t++)
        enc_step_kernel<<<128, 256>>>(t, p_xg_enc, enc_Whh);
    // 5) xg_pos = henc @ pos_Wih^T + biases
    gemm_nt_kernel<0,true><<<dim3(1, MTOK/128), 256>>>(
        p_henc, pos_Wih, pos_bih, pos_bhh, p_xg_pos, MTOK, G4P, HH);
    // 6) pos LSTM + heads + mu scan
    pos_kernel<<<1, 640>>>(pad_len, pos_Whh, W_mu, b_mu, W_sig, b_sig);
    // 7) attention weights
    attn_kernel<<<(BB*TT)/8, 256>>>(pad_len);
    // 8) ctx = g @ enc
    gemm_nn_kernel<<<dim3(HH/128, TT/128, BB), 256>>>(
        p_gw, p_henc, p_ctx, TT, HH, TT,
        (size_t)TT*TT, (size_t)TT*HH, (size_t)TT*HH);
    // 9) concat
    concat_kernel<<<(MTOK*128)/256, 256>>>();
    // 10) comb = tanh(cat @ W_cat^T + b_cat)
    gemm_nt_kernel<1,false><<<dim3(HH/128, MTOK/128), 256>>>(
        p_cat, W_cat, b_cat, nullptr, p_comb, MTOK, HH, 2*HH);
    // 11) A2 = split-bf16(comb)
    convA_kernel<<<(MTOK*128)/256, 256>>>();
    // 12) logits = A2 @ B2^T + dec_b  (tensor cores, 3-term bf16 split)
    dec_mma_kernel<<<dim3(MTOK/128, VV/128), 256>>>(p_A2, p_B2, dec_b, out);

    (void)in_sizes; (void)n_in; (void)out_size;
}

// round 12
// speedup vs baseline: 1.4424x; 1.0926x over previous
#include <cuda_runtime.h>
#include <cuda_bf16.h>
#include <cstdint>
#include <cstddef>

#define BB 8
#define TT 512
#define HH 512
#define VV 32000
#define PP 20
#define G4H 2048
#define G4P 80
#define MTOK (BB*TT)   // 4096
#define KD 1536        // decoder split-K: [hi | hi | lo]

// ---------------- scratch (static device globals; no allocations anywhere) ----------------
__device__ float d_emb[MTOK*HH];
__device__ float d_xg_enc[MTOK*G4H];
__device__ float d_henc[MTOK*HH];
__device__ float d_hglob[BB*HH];
__device__ float d_cstate[BB*HH];
__device__ float d_xg_pos[MTOK*G4P];
__device__ float d_mu[BB*TT];
__device__ float d_sg[BB*TT];
__device__ float d_gw[(size_t)BB*TT*TT];
__device__ float d_ctx[MTOK*HH];
__device__ float d_cat[MTOK*2*HH];
__device__ float d_comb[MTOK*HH];
__device__ __nv_bfloat16 d_A2[(size_t)MTOK*KD];   // comb split   [4096,1536]
__device__ __nv_bfloat16 d_B2[(size_t)VV*KD];     // emb split    [32000,1536]

__device__ __forceinline__ float sigmoidf_(float x) { return 1.f / (1.f + __expf(-x)); }

// ---------------- embedding gather ----------------
__global__ void gather_kernel(const int* __restrict__ tokens, const float* __restrict__ emb) {
    int m = blockIdx.x;
    int tok = tokens[m];
    const float4* src = reinterpret_cast<const float4*>(emb + (size_t)tok * HH);
    float4* dst = reinterpret_cast<float4*>(d_emb + (size_t)m * HH);
    dst[threadIdx.x] = src[threadIdx.x];
}

// ---------------- generic fp32 SGEMM: C = act(A[M,K] @ W[N,K]^T + b1 + b2) ----------------
template<int ACT, bool GUARD>
__global__ __launch_bounds__(256) void gemm_nt_kernel(
    const float* __restrict__ A, const float* __restrict__ W,
    const float* __restrict__ b1, const float* __restrict__ b2,
    float* __restrict__ C, int M, int N, int K)
{
    __shared__ float As[8][132];
    __shared__ float Ws[8][132];
    int tid = threadIdx.x;
    int m0 = blockIdx.y * 128, n0 = blockIdx.x * 128;
    int lrow = tid >> 1;
    int lk = (tid & 1) * 4;
    bool a_ok = !GUARD || (m0 + lrow) < M;
    bool w_ok = !GUARD || (n0 + lrow) < N;
    const float* Aptr = A + (size_t)(m0 + lrow) * K + lk;
    const float* Wptr = W + (size_t)(n0 + lrow) * K + lk;
    int tm = (tid >> 4) * 8;
    int tn = (tid & 15) * 8;

    float acc[8][8];
#pragma unroll
    for (int i = 0; i < 8; i++)
#pragma unroll
        for (int j = 0; j < 8; j++) acc[i][j] = 0.f;

    for (int kt = 0; kt < K; kt += 8) {
        float4 av = a_ok ? *reinterpret_cast<const float4*>(Aptr + kt) : make_float4(0,0,0,0);
        float4 wv = w_ok ? *reinterpret_cast<const float4*>(Wptr + kt) : make_float4(0,0,0,0);
        __syncthreads();
        As[lk+0][lrow] = av.x; As[lk+1][lrow] = av.y; As[lk+2][lrow] = av.z; As[lk+3][lrow] = av.w;
        Ws[lk+0][lrow] = wv.x; Ws[lk+1][lrow] = wv.y; Ws[lk+2][lrow] = wv.z; Ws[lk+3][lrow] = wv.w;
        __syncthreads();
#pragma unroll
        for (int k = 0; k < 8; k++) {
            float a[8], b[8];
            *reinterpret_cast<float4*>(&a[0]) = *reinterpret_cast<float4*>(&As[k][tm]);
            *reinterpret_cast<float4*>(&a[4]) = *reinterpret_cast<float4*>(&As[k][tm+4]);
            *reinterpret_cast<float4*>(&b[0]) = *reinterpret_cast<float4*>(&Ws[k][tn]);
            *reinterpret_cast<float4*>(&b[4]) = *reinterpret_cast<float4*>(&Ws[k][tn+4]);
#pragma unroll
            for (int i = 0; i < 8; i++)
#pragma unroll
                for (int j = 0; j < 8; j++) acc[i][j] += a[i] * b[j];
        }
    }

    float bias[8];
#pragma unroll
    for (int j = 0; j < 8; j++) {
        int gn = n0 + tn + j;
        float bv = 0.f;
        if (!GUARD || gn < N) {
            if (b1) bv += b1[gn];
            if (b2) bv += b2[gn];
        }
        bias[j] = bv;
    }

    if (!GUARD) {
#pragma unroll
        for (int i = 0; i < 8; i++) {
            float* crow = C + (size_t)(m0 + tm + i) * N + n0 + tn;
#pragma unroll
            for (int j4 = 0; j4 < 2; j4++) {
                float4 v;
                float v0 = acc[i][j4*4+0] + bias[j4*4+0];
                float v1 = acc[i][j4*4+1] + bias[j4*4+1];
                float v2 = acc[i][j4*4+2] + bias[j4*4+2];
                float v3 = acc[i][j4*4+3] + bias[j4*4+3];
                if (ACT == 1) { v0 = tanhf(v0); v1 = tanhf(v1); v2 = tanhf(v2); v3 = tanhf(v3); }
                v.x = v0; v.y = v1; v.z = v2; v.w = v3;
                *reinterpret_cast<float4*>(&crow[j4*4]) = v;
            }
        }
    } else {
#pragma unroll
        for (int i = 0; i < 8; i++) {
            int gm = m0 + tm + i;
            if (gm >= M) continue;
#pragma unroll
            for (int j = 0; j < 8; j++) {
                int gn = n0 + tn + j;
                if (gn >= N) continue;
                float v = acc[i][j] + bias[j];
                if (ACT == 1) v = tanhf(v);
                C[(size_t)gm * N + gn] = v;
            }
        }
    }
}

// ---------------- batched fp32 SGEMM: C[z] = A[z] @ B[z], B row-major [K,N] ----------------
__global__ __launch_bounds__(256) void gemm_nn_kernel(
    const float* __restrict__ Ab, const float* __restrict__ Bb, float* __restrict__ Cb,
    int M, int N, int K, size_t sA, size_t sB, size_t sC)
{
    __shared__ float As[8][132];
    __shared__ float Ws[8][132];
    const float* A = Ab + blockIdx.z * sA;
    const float* Bm = Bb + blockIdx.z * sB;
    float* C = Cb + blockIdx.z * sC;
    int tid = threadIdx.x;
    int m0 = blockIdx.y * 128, n0 = blockIdx.x * 128;
    int lrow = tid >> 1;
    int lk = (tid & 1) * 4;
    int bk = tid >> 5;
    int bn = (tid & 31) * 4;
    int tm = (tid >> 4) * 8;
    int tn = (tid & 15) * 8;

    float acc[8][8];
#pragma unroll
    for (int i = 0; i < 8; i++)
#pragma unroll
        for (int j = 0; j < 8; j++) acc[i][j] = 0.f;

    for (int kt = 0; kt < K; kt += 8) {
        float4 av = *reinterpret_cast<const float4*>(A + (size_t)(m0 + lrow) * K + kt + lk);
        float4 bv = *reinterpret_cast<const float4*>(Bm + (size_t)(kt + bk) * N + n0 + bn);
        __syncthreads();
        As[lk+0][lrow] = av.x; As[lk+1][lrow] = av.y; As[lk+2][lrow] = av.z; As[lk+3][lrow] = av.w;
        *reinterpret_cast<float4*>(&Ws[bk][bn]) = bv;
        __syncthreads();
#pragma unroll
        for (int k = 0; k < 8; k++) {
            float a[8], b[8];
            *reinterpret_cast<float4*>(&a[0]) = *reinterpret_cast<float4*>(&As[k][tm]);
            *reinterpret_cast<float4*>(&a[4]) = *reinterpret_cast<float4*>(&As[k][tm+4]);
            *reinterpret_cast<float4*>(&b[0]) = *reinterpret_cast<float4*>(&Ws[k][tn]);
            *reinterpret_cast<float4*>(&b[4]) = *reinterpret_cast<float4*>(&Ws[k][tn+4]);
#pragma unroll
            for (int i = 0; i < 8; i++)
#pragma unroll
                for (int j = 0; j < 8; j++) acc[i][j] += a[i] * b[j];
        }
    }
#pragma unroll
    for (int i = 0; i < 8; i++) {
        float* crow = C + (size_t)(m0 + tm + i) * N + n0 + tn;
#pragma unroll
        for (int j4 = 0; j4 < 2; j4++) {
            float4 v;
            v.x = acc[i][j4*4+0]; v.y = acc[i][j4*4+1];
            v.z = acc[i][j4*4+2]; v.w = acc[i][j4*4+3];
            *reinterpret_cast<float4*>(&crow[j4*4]) = v;
        }
    }
}

// ---------------- encoder LSTM: one launch per timestep (proven; cannot hang) ----------------
__global__ void enc_init_kernel() {
    int i = blockIdx.x * blockDim.x + threadIdx.x;
    if (i < BB * HH) { d_hglob[i] = 0.f; d_cstate[i] = 0.f; }
}

__global__ __launch_bounds__(256) void enc_step_kernel(
    int t, const float* __restrict__ xg, const float* __restrict__ Whh)
{
    __shared__ float h_s[BB * HH];
    __shared__ float red_s[16][8];
    int tid = threadIdx.x, cid = blockIdx.x;
    int lane = tid & 31, w = tid >> 5;

#pragma unroll
    for (int i = 0; i < 4; i++) {
        int idx = i * 256 + tid;
        reinterpret_cast<float4*>(h_s)[idx] = reinterpret_cast<const float4*>(d_hglob)[idx];
    }
    __syncthreads();

    int rl0 = w * 2, rl1 = w * 2 + 1;
    const float* wrow0 = Whh + (size_t)((rl0 >> 2) * HH + cid * 4 + (rl0 & 3)) * HH;
    const float* wrow1 = Whh + (size_t)((rl1 >> 2) * HH + cid * 4 + (rl1 & 3)) * HH;

    float acc0[8], acc1[8];
#pragma unroll
    for (int b = 0; b < 8; b++) { acc0[b] = 0.f; acc1[b] = 0.f; }

#pragma unroll
    for (int it = 0; it < 4; it++) {
        int k0 = it * 128 + lane * 4;
        float4 w0 = *reinterpret_cast<const float4*>(wrow0 + k0);
        float4 w1 = *reinterpret_cast<const float4*>(wrow1 + k0);
#pragma unroll
        for (int b = 0; b < 8; b++) {
            float4 hv = *reinterpret_cast<const float4*>(&h_s[b * HH + k0]);
            acc0[b] += w0.x*hv.x + w0.y*hv.y + w0.z*hv.z + w0.w*hv.w;
            acc1[b] += w1.x*hv.x + w1.y*hv.y + w1.z*hv.z + w1.w*hv.w;
        }
    }
#pragma unroll
    for (int b = 0; b < 8; b++) {
        float v0 = acc0[b], v1 = acc1[b];
#pragma unroll
        for (int o = 16; o; o >>= 1) {
            v0 += __shfl_xor_sync(0xffffffffu, v0, o);
            v1 += __shfl_xor_sync(0xffffffffu, v1, o);
        }
        if (lane == 0) { red_s[rl0][b] = v0; red_s[rl1][b] = v1; }
    }
    __syncthreads();

    if (tid < 32) {
        int b = tid >> 2, j2 = tid & 3;
        float g4[4];
#pragma unroll
        for (int q = 0; q < 4; q++)
            g4[q] = xg[((size_t)(b*TT + t))*G4H + q*HH + cid*4 + j2] + red_s[q*4 + j2][b];
        float ii = sigmoidf_(g4[0]);
        float ff = sigmoidf_(g4[1]);
        float gg = tanhf(g4[2]);
        float oo = sigmoidf_(g4[3]);
        int hidx = cid*4 + j2;
        float c = ff * d_cstate[b*HH + hidx] + ii * gg;
        float h = oo * tanhf(c);
        d_cstate[b*HH + hidx] = c;
        d_hglob[b*HH + hidx]  = h;
        d_henc[((size_t)(b*TT + t))*HH + hidx] = h;
    }
}

// ---------------- pos LSTM + heads + mu scan: one CTA PER BATCH (independent chains) -------
__global__ __launch_bounds__(128) void pos_kernel(
    const int* __restrict__ pad_len, const float* __restrict__ Whh,
    const float* __restrict__ Wmu, const float* __restrict__ bmu,
    const float* __restrict__ Wsig, const float* __restrict__ bsig)
{
    __shared__ float Whh_s[G4P][PP + 1];
    __shared__ float Wmu_s[3][PP], Wsig_s[PP];
    __shared__ float hp[PP], cpv[PP], gate[G4P];
    __shared__ float head[4];
    __shared__ float bmu_s[3], bsig_s;
    int b = blockIdx.x;
    int tid = threadIdx.x;

    for (int i = tid; i < G4P*PP; i += 128) Whh_s[i / PP][i % PP] = Whh[i];
    for (int i = tid; i < 3*PP;   i += 128) Wmu_s[i / PP][i % PP] = Wmu[i];
    if (tid < PP) { Wsig_s[tid] = Wsig[tid]; hp[tid] = 0.f; cpv[tid] = 0.f; }
    if (tid < 3) bmu_s[tid] = bmu[tid];
    if (tid == 0) bsig_s = bsig[0];
    float L = (float)pad_len[b];
    float mu_prev = 0.f;   // only tid 0 uses it
    __syncthreads();

    const float* xgb = d_xg_pos + (size_t)b * TT * G4P;
    for (int t = 0; t < TT; t++) {
        if (tid < G4P) {
            float acc = __ldg(&xgb[(size_t)t * G4P + tid]);
            const float* wr = Whh_s[tid];
#pragma unroll
            for (int k = 0; k < PP; k++) acc += wr[k] * hp[k];
            gate[tid] = acc;
        }
        __syncthreads();
        if (tid < PP) {
            float ii = sigmoidf_(gate[tid]);
            float ff = sigmoidf_(gate[PP + tid]);
            float gg = tanhf(gate[2*PP + tid]);
            float oo = sigmoidf_(gate[3*PP + tid]);
            float c = ff * cpv[tid] + ii * gg;
            cpv[tid] = c;
            hp[tid] = oo * tanhf(c);
        }
        __syncthreads();
        if (tid < 4) {
            float s = (tid < 3) ? bmu_s[tid] : bsig_s;
            const float* wv = (tid < 3) ? Wmu_s[tid] : Wsig_s;
#pragma unroll
            for (int p = 0; p < PP; p++) s += hp[p] * wv[p];
            head[tid] = s;
        }
        __syncthreads();
        if (tid == 0) {
            float m0 = fmaxf(head[0], 0.f);
            float m1 = fmaxf(head[1], 0.f);
            float m2 = fmaxf(head[2], 0.f);
            float sgv = sigmoidf_(head[3]);
            float mu = m0*mu_prev + m1/L + m2*((float)(t+1))/L;
            mu = fmaxf(mu, (float)t / L);
            mu_prev = mu;
            d_mu[b*TT + t] = mu;
            d_sg[b*TT + t] = sgv;
        }
        __syncthreads();
    }
}

// ---------------- normalized Gaussian prefix weights ----------------
__global__ void attn_kernel(const int* __restrict__ pad_len) {
    int wq = blockIdx.x * 8 + (threadIdx.x >> 5);
    int lane = threadIdx.x & 31;
    int b = wq >> 9, tq = wq & 511;
    float L = (float)pad_len[b];
    float mu = d_mu[b*TT + tq], sg = d_sg[b*TT + tq];
    float denom = 2.f * sg * sg + 0.001f;
    float* grow = &d_gw[((size_t)(b*TT + tq)) * TT];
    float wv[16];
    float sum = 0.f;
#pragma unroll
    for (int i = 0; i < 16; i++) {
        int tk = lane + i*32;
        float dd = (float)tk / L - mu;
        float v = (tk <= tq) ? __expf(-dd*dd / denom) : 0.f;
        wv[i] = v; sum += v;
    }
#pragma unroll
    for (int o = 16; o; o >>= 1) sum += __shfl_xor_sync(0xffffffffu, sum, o);
    float inv = 1.f / fmaxf(sum, 1e-12f);
#pragma unroll
    for (int i = 0; i < 16; i++) grow[lane + i*32] = wv[i] * inv;
}

// ---------------- concat [ctx, enc] ----------------
__global__ void concat_kernel() {
    int idx = blockIdx.x * blockDim.x + threadIdx.x;
    if (idx >= MTOK * 128) return;
    int m = idx >> 7, h4 = idx & 127;
    float4 c4 = *reinterpret_cast<const float4*>(&d_ctx[((size_t)m << 9) + (h4 << 2)]);
    float4 e4 = *reinterpret_cast<const float4*>(&d_henc[((size_t)m << 9) + (h4 << 2)]);
    *reinterpret_cast<float4*>(&d_cat[(size_t)m*1024 + (h4 << 2)]) = c4;
    *reinterpret_cast<float4*>(&d_cat[(size_t)m*1024 + 512 + (h4 << 2)]) = e4;
}

// ---------------- fp32 -> split-bf16 converts ----------------
// A2 layout: [0,512)=hi, [512,1024)=hi, [1024,1536)=lo
// B2 layout: [0,512)=hi, [512,1024)=lo, [1024,1536)=hi
__device__ __forceinline__ void split_bf16(float a, unsigned short& h, unsigned short& l) {
    __nv_bfloat16 hb = __float2bfloat16_rn(a);
    float lo = a - __bfloat162float(hb);
    __nv_bfloat16 lb = __float2bfloat16_rn(lo);
    h = *reinterpret_cast<unsigned short*>(&hb);
    l = *reinterpret_cast<unsigned short*>(&lb);
}

__global__ void convA_kernel() {   // comb [4096,512] -> d_A2
    int i = blockIdx.x * 256 + threadIdx.x;
    int m = i >> 7, k4 = (i & 127) * 4;
    float4 v = *reinterpret_cast<const float4*>(&d_comb[(size_t)m*HH + k4]);
    unsigned short h[4], l[4];
    split_bf16(v.x, h[0], l[0]); split_bf16(v.y, h[1], l[1]);
    split_bf16(v.z, h[2], l[2]); split_bf16(v.w, h[3], l[3]);
    ushort4 H = make_ushort4(h[0], h[1], h[2], h[3]);
    ushort4 Lo = make_ushort4(l[0], l[1], l[2], l[3]);
    __nv_bfloat16* base = d_A2 + (size_t)m * KD + k4;
    *reinterpret_cast<ushort4*>(base)        = H;
    *reinterpret_cast<ushort4*>(base + 512)  = H;
    *reinterpret_cast<ushort4*>(base + 1024) = Lo;
}

__global__ void convB_kernel(const float* __restrict__ emb) {  // emb [32000,512] -> d_B2
    int i = blockIdx.x * 256 + threadIdx.x;
    int n = i >> 7, k4 = (i & 127) * 4;
    float4 v = *reinterpret_cast<const float4*>(&emb[(size_t)n*HH + k4]);
    unsigned short h[4], l[4];
    split_bf16(v.x, h[0], l[0]); split_bf16(v.y, h[1], l[1]);
    split_bf16(v.z, h[2], l[2]); split_bf16(v.w, h[3], l[3]);
    ushort4 H = make_ushort4(h[0], h[1], h[2], h[3]);
    ushort4 Lo = make_ushort4(l[0], l[1], l[2], l[3]);
    __nv_bfloat16* base = d_B2 + (size_t)n * KD + k4;
    *reinterpret_cast<ushort4*>(base)        = H;
    *reinterpret_cast<ushort4*>(base + 512)  = Lo;
    *reinterpret_cast<ushort4*>(base + 1024) = H;
}

// ---------------- decoder: bf16 NT GEMM, cp.async 2-stage pipeline, fp32 accum -------------
__device__ __forceinline__ void ldsm_x4(uint32_t& r0, uint32_t& r1, uint32_t& r2, uint32_t& r3,
                                        uint32_t addr) {
    asm volatile("ldmatrix.sync.aligned.m8n8.x4.shared.b16 {%0,%1,%2,%3}, [%4];"
                 : "=r"(r0), "=r"(r1), "=r"(r2), "=r"(r3) : "r"(addr));
}
__device__ __forceinline__ void ldsm_x2(uint32_t& r0, uint32_t& r1, uint32_t addr) {
    asm volatile("ldmatrix.sync.aligned.m8n8.x2.shared.b16 {%0,%1}, [%2];"
                 : "=r"(r0), "=r"(r1) : "r"(addr));
}
__device__ __forceinline__ void mma_bf16(float* c, const uint32_t* a, const uint32_t* b) {
    asm volatile(
        "mma.sync.aligned.m16n8k16.row.col.f32.bf16.bf16.f32 "
        "{%0,%1,%2,%3}, {%4,%5,%6,%7}, {%8,%9}, {%0,%1,%2,%3};"
        : "+f"(c[0]), "+f"(c[1]), "+f"(c[2]), "+f"(c[3])
        : "r"(a[0]), "r"(a[1]), "r"(a[2]), "r"(a[3]), "r"(b[0]), "r"(b[1]));
}
__device__ __forceinline__ void cp_async16(uint32_t s, const void* g) {
    asm volatile("cp.async.cg.shared.global [%0], [%1], 16;" :: "r"(s), "l"(g));
}
#define CP_COMMIT() asm volatile("cp.async.commit_group;" ::: "memory")
#define CP_WAIT0()  asm volatile("cp.async.wait_group 0;" ::: "memory")

#define STG_BYTES (128*40*2)   // one stage of As or Bs

// BM=BN=128, BK=32, 256 threads (8 warps, 2x4), warp tile 64x32, K=1536 (48 iters).
__global__ __launch_bounds__(256) void dec_mma_kernel(
    const __nv_bfloat16* __restrict__ A, const __nv_bfloat16* __restrict__ B,
    const float* __restrict__ bias, float* __restrict__ C)
{
    __shared__ __align__(16) __nv_bfloat16 As[2][128][40];   // 20 KB
    __shared__ __align__(16) __nv_bfloat16 Bs[2][128][40];   // 20 KB
    int tid = threadIdx.x, lane = tid & 31, w = tid >> 5;
    int wm = w >> 2, wn = w & 3;
    int m0 = blockIdx.x * 128, n0 = blockIdx.y * 128;

    int lr = tid >> 2;              // 0..63
    int lc = (tid & 3) * 8;         // bf16 col offset {0,8,16,24} (16B aligned)
    const __nv_bfloat16* Ag = A + (size_t)(m0 + lr) * KD + lc;
    const __nv_bfloat16* Bg = B + (size_t)(n0 + lr) * KD + lc;

    uint32_t sA0 = (uint32_t)__cvta_generic_to_shared(&As[0][0][0]);
    uint32_t sB0 = (uint32_t)__cvta_generic_to_shared(&Bs[0][0][0]);
    uint32_t offLo = (uint32_t)(lr * 40 + lc) * 2;
    uint32_t offHi = (uint32_t)((lr + 64) * 40 + lc) * 2;

    float acc[4][4][4];
#pragma unroll
    for (int i = 0; i < 4; i++)
#pragma unroll
        for (int j = 0; j < 4; j++) { acc[i][j][0]=0.f; acc[i][j][1]=0.f; acc[i][j][2]=0.f; acc[i][j][3]=0.f; }

    // prologue: async-load stage 0
    {
        cp_async16(sA0 + offLo, Ag);
        cp_async16(sA0 + offHi, Ag + (size_t)64 * KD);
        cp_async16(sB0 + offLo, Bg);
        cp_async16(sB0 + offHi, Bg + (size_t)64 * KD);
        CP_COMMIT();
    }

    for (int kt = 0; kt < 48; kt++) {
        int buf = kt & 1;
        CP_WAIT0();          // stage kt's loads complete (this thread's)
        __syncthreads();     // all threads' loads visible; all done computing kt-1

        if (kt < 47) {       // issue stage kt+1 into the other buffer (overlaps compute)
            int nb = (kt + 1) & 1;
            const __nv_bfloat16* Agn = Ag + (kt + 1) * 32;
            const __nv_bfloat16* Bgn = Bg + (kt + 1) * 32;
            cp_async16(sA0 + nb * STG_BYTES + offLo, Agn);
            cp_async16(sA0 + nb * STG_BYTES + offHi, Agn + (size_t)64 * KD);
            cp_async16(sB0 + nb * STG_BYTES + offLo, Bgn);
            cp_async16(sB0 + nb * STG_BYTES + offHi, Bgn + (size_t)64 * KD);
            CP_COMMIT();
        }

        uint32_t sAb = sA0 + (uint32_t)buf * STG_BYTES;
        uint32_t sBb = sB0 + (uint32_t)buf * STG_BYTES;
#pragma unroll
        for (int k16 = 0; k16 < 2; k16++) {
            uint32_t af[4][4], bf[4][2];
#pragma unroll
            for (int mt = 0; mt < 4; mt++) {
                uint32_t addr = sAb + ((wm*64 + mt*16 + (lane & 15)) * 40 + k16*16 + (lane >> 4)*8) * 2;
                ldsm_x4(af[mt][0], af[mt][1], af[mt][2], af[mt][3], addr);
            }
#pragma unroll
            for (int nt = 0; nt < 4; nt++) {
                uint32_t addr = sBb + ((wn*32 + nt*8 + (lane & 7)) * 40 + k16*16 + ((lane >> 3) & 1)*8) * 2;
                ldsm_x2(bf[nt][0], bf[nt][1], addr);
            }
#pragma unroll
            for (int mt = 0; mt < 4; mt++)
#pragma unroll
                for (int nt = 0; nt < 4; nt++)
                    mma_bf16(acc[mt][nt], af[mt], bf[nt]);
        }
    }

    // epilogue: += bias, store fp32
#pragma unroll
    for (int mt = 0; mt < 4; mt++) {
        int r0 = m0 + wm*64 + mt*16 + (lane >> 2);
#pragma unroll
        for (int nt = 0; nt < 4; nt++) {
            int cc = n0 + wn*32 + nt*8 + (lane & 3)*2;
            float b0 = bias[cc], b1 = bias[cc + 1];
            float2 v0 = make_float2(acc[mt][nt][0] + b0, acc[mt][nt][1] + b1);
            float2 v1 = make_float2(acc[mt][nt][2] + b0, acc[mt][nt][3] + b1);
            *reinterpret_cast<float2*>(&C[(size_t)r0 * VV + cc])       = v0;
            *reinterpret_cast<float2*>(&C[(size_t)(r0 + 8) * VV + cc]) = v1;
        }
    }
}

// ---------------- launcher ----------------
extern "C" void kernel_launch(void* const* d_in, const int* in_sizes, int n_in,
                              void* d_out, int out_size)
{
    const int*   tokens   = (const int*)d_in[0];
    const int*   pad_len  = (const int*)d_in[1];
    const float* embedding= (const float*)d_in[2];
    const float* enc_Wih  = (const float*)d_in[3];
    const float* enc_Whh  = (const float*)d_in[4];
    const float* enc_bih  = (const float*)d_in[5];
    const float* enc_bhh  = (const float*)d_in[6];
    const float* pos_Wih  = (const float*)d_in[7];
    const float* pos_Whh  = (const float*)d_in[8];
    const float* pos_bih  = (const float*)d_in[9];
    const float* pos_bhh  = (const float*)d_in[10];
    const float* W_mu     = (const float*)d_in[11];
    const float* b_mu     = (const float*)d_in[12];
    const float* W_sig    = (const float*)d_in[13];
    const float* b_sig    = (const float*)d_in[14];
    const float* W_cat    = (const float*)d_in[15];
    const float* b_cat    = (const float*)d_in[16];
    const float* dec_b    = (const float*)d_in[17];
    float* out = (float*)d_out;

    float *p_emb, *p_xg_enc, *p_henc, *p_xg_pos, *p_gw, *p_ctx, *p_cat, *p_comb;
    __nv_bfloat16 *p_A2, *p_B2;
    cudaGetSymbolAddress((void**)&p_emb,    d_emb);
    cudaGetSymbolAddress((void**)&p_xg_enc, d_xg_enc);
    cudaGetSymbolAddress((void**)&p_henc,   d_henc);
    cudaGetSymbolAddress((void**)&p_xg_pos, d_xg_pos);
    cudaGetSymbolAddress((void**)&p_gw,     d_gw);
    cudaGetSymbolAddress((void**)&p_ctx,    d_ctx);
    cudaGetSymbolAddress((void**)&p_cat,    d_cat);
    cudaGetSymbolAddress((void**)&p_comb,   d_comb);
    cudaGetSymbolAddress((void**)&p_A2,     d_A2);
    cudaGetSymbolAddress((void**)&p_B2,     d_B2);

    // 1) gather embeddings
    gather_kernel<<<MTOK, 128>>>(tokens, embedding);
    // 2) B2 = split-bf16(embedding)
    convB_kernel<<<(VV*128)/256, 256>>>(embedding);
    // 3) xg_enc = emb @ enc_Wih^T + biases
    gemm_nt_kernel<0,false><<<dim3(G4H/128, MTOK/128), 256>>>(
        p_emb, enc_Wih, enc_bih, enc_bhh, p_xg_enc, MTOK, G4H, HH);
    // 4) encoder LSTM: init + 512 sequential step launches (proven path)
    enc_init_kernel<<<(BB*HH + 255)/256, 256>>>();
    for (int t = 0; t < TT; t++)
        enc_step_kernel<<<128, 256>>>(t, p_xg_enc, enc_Whh);
    // 5) xg_pos = henc @ pos_Wih^T + biases
    gemm_nt_kernel<0,true><<<dim3(1, MTOK/128), 256>>>(
        p_henc, pos_Wih, pos_bih, pos_bhh, p_xg_pos, MTOK, G4P, HH);
    // 6) pos LSTM + heads + mu scan (one CTA per batch)
    pos_kernel<<<BB, 128>>>(pad_len, pos_Whh, W_mu, b_mu, W_sig, b_sig);
    // 7) attention weights
    attn_kernel<<<(BB*TT)/8, 256>>>(pad_len);
    // 8) ctx = g @ enc
    gemm_nn_kernel<<<dim3(HH/128, TT/128, BB), 256>>>(
        p_gw, p_henc, p_ctx, TT, HH, TT,
        (size_t)TT*TT, (size_t)TT*HH, (size_t)TT*HH);
    // 9) concat
    concat_kernel<<<(MTOK*128)/256, 256>>>();
    // 10) comb = tanh(cat @ W_cat^T + b_cat)
    gemm_nt_kernel<1,false><<<dim3(HH/128, MTOK/128), 256>>>(
        p_cat, W_cat, b_cat, nullptr, p_comb, MTOK, HH, 2*HH);
    // 11) A2 = split-bf16(comb)
    convA_kernel<<<(MTOK*128)/256, 256>>>();
    // 12) logits = A2 @ B2^T + dec_b  (tensor cores, cp.async pipelined)
    dec_mma_kernel<<<dim3(MTOK/128, VV/128), 256>>>(p_A2, p_B2, dec_b, out);

    (void)in_sizes; (void)n_in; (void)out_size;
}

// round 13
// speedup vs baseline: 1.5234x; 1.0561x over previous
#include <cuda_runtime.h>
#include <cuda_bf16.h>
#include <cstdint>
#include <cstddef>

#define BB 8
#define TT 512
#define HH 512
#define VV 32000
#define PP 20
#define G4H 2048
#define G4P 80
#define MTOK (BB*TT)   // 4096

// ---------------- scratch (static device globals; no allocations anywhere) ----------------
__device__ float d_emb[MTOK*HH];
__device__ float d_xg_enc[MTOK*G4H];
__device__ float d_henc[MTOK*HH];
__device__ float d_hglob[BB*HH];
__device__ float d_cstate[BB*HH];
__device__ float d_xg_pos[MTOK*G4P];
__device__ float d_mu[BB*TT];
__device__ float d_sg[BB*TT];
__device__ float d_gw[(size_t)BB*TT*TT];
__device__ float d_ctx[MTOK*HH];
__device__ float d_cat[MTOK*2*HH];
__device__ float d_comb[MTOK*HH];
__device__ __nv_bfloat16 d_A2[(size_t)MTOK*1536];      // A-side splits (emb_g, later comb)
__device__ __nv_bfloat16 d_B2[(size_t)VV*1536];        // embedding split
__device__ __nv_bfloat16 d_W2ih[(size_t)G4H*1536];     // enc_Wih split
__device__ __nv_bfloat16 d_cat2[(size_t)MTOK*3072];    // cat split
__device__ __nv_bfloat16 d_Wcat2[(size_t)HH*3072];     // W_cat split

__device__ __forceinline__ float sigmoidf_(float x) { return 1.f / (1.f + __expf(-x)); }

// ---------------- embedding gather ----------------
__global__ void gather_kernel(const int* __restrict__ tokens, const float* __restrict__ emb) {
    int m = blockIdx.x;
    int tok = tokens[m];
    const float4* src = reinterpret_cast<const float4*>(emb + (size_t)tok * HH);
    float4* dst = reinterpret_cast<float4*>(d_emb + (size_t)m * HH);
    dst[threadIdx.x] = src[threadIdx.x];
}

// ---------------- fp32 SGEMM (kept for small/guarded cases): C = A @ W^T + b ----------------
template<int ACT, bool GUARD>
__global__ __launch_bounds__(256) void gemm_nt_kernel(
    const float* __restrict__ A, const float* __restrict__ W,
    const float* __restrict__ b1, const float* __restrict__ b2,
    float* __restrict__ C, int M, int N, int K)
{
    __shared__ float As[8][132];
    __shared__ float Ws[8][132];
    int tid = threadIdx.x;
    int m0 = blockIdx.y * 128, n0 = blockIdx.x * 128;
    int lrow = tid >> 1;
    int lk = (tid & 1) * 4;
    bool a_ok = !GUARD || (m0 + lrow) < M;
    bool w_ok = !GUARD || (n0 + lrow) < N;
    const float* Aptr = A + (size_t)(m0 + lrow) * K + lk;
    const float* Wptr = W + (size_t)(n0 + lrow) * K + lk;
    int tm = (tid >> 4) * 8;
    int tn = (tid & 15) * 8;

    float acc[8][8];
#pragma unroll
    for (int i = 0; i < 8; i++)
#pragma unroll
        for (int j = 0; j < 8; j++) acc[i][j] = 0.f;

    for (int kt = 0; kt < K; kt += 8) {
        float4 av = a_ok ? *reinterpret_cast<const float4*>(Aptr + kt) : make_float4(0,0,0,0);
        float4 wv = w_ok ? *reinterpret_cast<const float4*>(Wptr + kt) : make_float4(0,0,0,0);
        __syncthreads();
        As[lk+0][lrow] = av.x; As[lk+1][lrow] = av.y; As[lk+2][lrow] = av.z; As[lk+3][lrow] = av.w;
        Ws[lk+0][lrow] = wv.x; Ws[lk+1][lrow] = wv.y; Ws[lk+2][lrow] = wv.z; Ws[lk+3][lrow] = wv.w;
        __syncthreads();
#pragma unroll
        for (int k = 0; k < 8; k++) {
            float a[8], b[8];
            *reinterpret_cast<float4*>(&a[0]) = *reinterpret_cast<float4*>(&As[k][tm]);
            *reinterpret_cast<float4*>(&a[4]) = *reinterpret_cast<float4*>(&As[k][tm+4]);
            *reinterpret_cast<float4*>(&b[0]) = *reinterpret_cast<float4*>(&Ws[k][tn]);
            *reinterpret_cast<float4*>(&b[4]) = *reinterpret_cast<float4*>(&Ws[k][tn+4]);
#pragma unroll
            for (int i = 0; i < 8; i++)
#pragma unroll
                for (int j = 0; j < 8; j++) acc[i][j] += a[i] * b[j];
        }
    }

    float bias[8];
#pragma unroll
    for (int j = 0; j < 8; j++) {
        int gn = n0 + tn + j;
        float bv = 0.f;
        if (!GUARD || gn < N) {
            if (b1) bv += b1[gn];
            if (b2) bv += b2[gn];
        }
        bias[j] = bv;
    }

#pragma unroll
    for (int i = 0; i < 8; i++) {
        int gm = m0 + tm + i;
        if (GUARD && gm >= M) continue;
#pragma unroll
        for (int j = 0; j < 8; j++) {
            int gn = n0 + tn + j;
            if (GUARD && gn >= N) continue;
            float v = acc[i][j] + bias[j];
            if (ACT == 1) v = tanhf(v);
            C[(size_t)gm * N + gn] = v;
        }
    }
}

// ---------------- batched fp32 SGEMM: ctx = g @ enc ----------------
__global__ __launch_bounds__(256) void gemm_nn_kernel(
    const float* __restrict__ Ab, const float* __restrict__ Bb, float* __restrict__ Cb,
    int M, int N, int K, size_t sA, size_t sB, size_t sC)
{
    __shared__ float As[8][132];
    __shared__ float Ws[8][132];
    const float* A = Ab + blockIdx.z * sA;
    const float* Bm = Bb + blockIdx.z * sB;
    float* C = Cb + blockIdx.z * sC;
    int tid = threadIdx.x;
    int m0 = blockIdx.y * 128, n0 = blockIdx.x * 128;
    int lrow = tid >> 1;
    int lk = (tid & 1) * 4;
    int bk = tid >> 5;
    int bn = (tid & 31) * 4;
    int tm = (tid >> 4) * 8;
    int tn = (tid & 15) * 8;

    float acc[8][8];
#pragma unroll
    for (int i = 0; i < 8; i++)
#pragma unroll
        for (int j = 0; j < 8; j++) acc[i][j] = 0.f;

    for (int kt = 0; kt < K; kt += 8) {
        float4 av = *reinterpret_cast<const float4*>(A + (size_t)(m0 + lrow) * K + kt + lk);
        float4 bv = *reinterpret_cast<const float4*>(Bm + (size_t)(kt + bk) * N + n0 + bn);
        __syncthreads();
        As[lk+0][lrow] = av.x; As[lk+1][lrow] = av.y; As[lk+2][lrow] = av.z; As[lk+3][lrow] = av.w;
        *reinterpret_cast<float4*>(&Ws[bk][bn]) = bv;
        __syncthreads();
#pragma unroll
        for (int k = 0; k < 8; k++) {
            float a[8], b[8];
            *reinterpret_cast<float4*>(&a[0]) = *reinterpret_cast<float4*>(&As[k][tm]);
            *reinterpret_cast<float4*>(&a[4]) = *reinterpret_cast<float4*>(&As[k][tm+4]);
            *reinterpret_cast<float4*>(&b[0]) = *reinterpret_cast<float4*>(&Ws[k][tn]);
            *reinterpret_cast<float4*>(&b[4]) = *reinterpret_cast<float4*>(&Ws[k][tn+4]);
#pragma unroll
            for (int i = 0; i < 8; i++)
#pragma unroll
                for (int j = 0; j < 8; j++) acc[i][j] += a[i] * b[j];
        }
    }
#pragma unroll
    for (int i = 0; i < 8; i++) {
        float* crow = C + (size_t)(m0 + tm + i) * N + n0 + tn;
#pragma unroll
        for (int j4 = 0; j4 < 2; j4++) {
            float4 v;
            v.x = acc[i][j4*4+0]; v.y = acc[i][j4*4+1];
            v.z = acc[i][j4*4+2]; v.w = acc[i][j4*4+3];
            *reinterpret_cast<float4*>(&crow[j4*4]) = v;
        }
    }
}

// ---------------- encoder LSTM: one launch per timestep, register-prefetched ----------------
__global__ void enc_init_kernel() {
    int i = blockIdx.x * blockDim.x + threadIdx.x;
    if (i < BB * HH) { d_hglob[i] = 0.f; d_cstate[i] = 0.f; }
}

__global__ __launch_bounds__(256) void enc_step_kernel(
    int t, const float* __restrict__ xg, const float* __restrict__ Whh)
{
    __shared__ float h_s[BB * HH];
    __shared__ float red_s[16][8];
    int tid = threadIdx.x, cid = blockIdx.x;
    int lane = tid & 31, w = tid >> 5;

    int rl0 = w * 2, rl1 = w * 2 + 1;
    const float* wrow0 = Whh + (size_t)((rl0 >> 2) * HH + cid * 4 + (rl0 & 3)) * HH;
    const float* wrow1 = Whh + (size_t)((rl1 >> 2) * HH + cid * 4 + (rl1 & 3)) * HH;

    // prefetch weights + xg into registers BEFORE the h staging sync (overlap L2 latency)
    float4 wv0[4], wv1[4];
#pragma unroll
    for (int it = 0; it < 4; it++) {
        int k0 = it * 128 + lane * 4;
        wv0[it] = __ldg(reinterpret_cast<const float4*>(wrow0 + k0));
        wv1[it] = __ldg(reinterpret_cast<const float4*>(wrow1 + k0));
    }
    float xgv[4];
    if (tid < 32) {
        int b = tid >> 2, j2 = tid & 3;
#pragma unroll
        for (int q = 0; q < 4; q++)
            xgv[q] = __ldg(&xg[((size_t)(b*TT + t))*G4H + q*HH + cid*4 + j2]);
    }

#pragma unroll
    for (int i = 0; i < 4; i++) {
        int idx = i * 256 + tid;
        reinterpret_cast<float4*>(h_s)[idx] = reinterpret_cast<const float4*>(d_hglob)[idx];
    }
    __syncthreads();

    float acc0[8], acc1[8];
#pragma unroll
    for (int b = 0; b < 8; b++) { acc0[b] = 0.f; acc1[b] = 0.f; }

#pragma unroll
    for (int it = 0; it < 4; it++) {
        int k0 = it * 128 + lane * 4;
        float4 w0 = wv0[it], w1 = wv1[it];
#pragma unroll
        for (int b = 0; b < 8; b++) {
            float4 hv = *reinterpret_cast<const float4*>(&h_s[b * HH + k0]);
            acc0[b] += w0.x*hv.x + w0.y*hv.y + w0.z*hv.z + w0.w*hv.w;
            acc1[b] += w1.x*hv.x + w1.y*hv.y + w1.z*hv.z + w1.w*hv.w;
        }
    }
#pragma unroll
    for (int b = 0; b < 8; b++) {
        float v0 = acc0[b], v1 = acc1[b];
#pragma unroll
        for (int o = 16; o; o >>= 1) {
            v0 += __shfl_xor_sync(0xffffffffu, v0, o);
            v1 += __shfl_xor_sync(0xffffffffu, v1, o);
        }
        if (lane == 0) { red_s[rl0][b] = v0; red_s[rl1][b] = v1; }
    }
    __syncthreads();

    if (tid < 32) {
        int b = tid >> 2, j2 = tid & 3;
        float g4[4];
#pragma unroll
        for (int q = 0; q < 4; q++)
            g4[q] = xgv[q] + red_s[q*4 + j2][b];
        float ii = sigmoidf_(g4[0]);
        float ff = sigmoidf_(g4[1]);
        float gg = tanhf(g4[2]);
        float oo = sigmoidf_(g4[3]);
        int hidx = cid*4 + j2;
        float c = ff * d_cstate[b*HH + hidx] + ii * gg;
        float h = oo * tanhf(c);
        d_cstate[b*HH + hidx] = c;
        d_hglob[b*HH + hidx]  = h;
        d_henc[((size_t)(b*TT + t))*HH + hidx] = h;
    }
}

// ---------------- pos LSTM + heads + mu scan: one CTA per batch ----------------
__global__ __launch_bounds__(128) void pos_kernel(
    const int* __restrict__ pad_len, const float* __restrict__ Whh,
    const float* __restrict__ Wmu, const float* __restrict__ bmu,
    const float* __restrict__ Wsig, const float* __restrict__ bsig)
{
    __shared__ float Whh_s[G4P][PP + 1];
    __shared__ float Wmu_s[3][PP], Wsig_s[PP];
    __shared__ float hp[PP], cpv[PP], gate[G4P];
    __shared__ float head[4];
    __shared__ float bmu_s[3], bsig_s;
    int b = blockIdx.x;
    int tid = threadIdx.x;

    for (int i = tid; i < G4P*PP; i += 128) Whh_s[i / PP][i % PP] = Whh[i];
    for (int i = tid; i < 3*PP;   i += 128) Wmu_s[i / PP][i % PP] = Wmu[i];
    if (tid < PP) { Wsig_s[tid] = Wsig[tid]; hp[tid] = 0.f; cpv[tid] = 0.f; }
    if (tid < 3) bmu_s[tid] = bmu[tid];
    if (tid == 0) bsig_s = bsig[0];
    float L = (float)pad_len[b];
    float mu_prev = 0.f;
    __syncthreads();

    const float* xgb = d_xg_pos + (size_t)b * TT * G4P;
    for (int t = 0; t < TT; t++) {
        if (tid < G4P) {
            float acc = __ldg(&xgb[(size_t)t * G4P + tid]);
            const float* wr = Whh_s[tid];
#pragma unroll
            for (int k = 0; k < PP; k++) acc += wr[k] * hp[k];
            gate[tid] = acc;
        }
        __syncthreads();
        if (tid < PP) {
            float ii = sigmoidf_(gate[tid]);
            float ff = sigmoidf_(gate[PP + tid]);
            float gg = tanhf(gate[2*PP + tid]);
            float oo = sigmoidf_(gate[3*PP + tid]);
            float c = ff * cpv[tid] + ii * gg;
            cpv[tid] = c;
            hp[tid] = oo * tanhf(c);
        }
        __syncthreads();
        if (tid < 4) {
            float s = (tid < 3) ? bmu_s[tid] : bsig_s;
            const float* wv = (tid < 3) ? Wmu_s[tid] : Wsig_s;
#pragma unroll
            for (int p = 0; p < PP; p++) s += hp[p] * wv[p];
            head[tid] = s;
        }
        __syncthreads();
        if (tid == 0) {
            float m0 = fmaxf(head[0], 0.f);
            float m1 = fmaxf(head[1], 0.f);
            float m2 = fmaxf(head[2], 0.f);
            float sgv = sigmoidf_(head[3]);
            float mu = m0*mu_prev + m1/L + m2*((float)(t+1))/L;
            mu = fmaxf(mu, (float)t / L);
            mu_prev = mu;
            d_mu[b*TT + t] = mu;
            d_sg[b*TT + t] = sgv;
        }
        __syncthreads();
    }
}

// ---------------- normalized Gaussian prefix weights ----------------
__global__ void attn_kernel(const int* __restrict__ pad_len) {
    int wq = blockIdx.x * 8 + (threadIdx.x >> 5);
    int lane = threadIdx.x & 31;
    int b = wq >> 9, tq = wq & 511;
    float L = (float)pad_len[b];
    float mu = d_mu[b*TT + tq], sg = d_sg[b*TT + tq];
    float denom = 2.f * sg * sg + 0.001f;
    float* grow = &d_gw[((size_t)(b*TT + tq)) * TT];
    float wv[16];
    float sum = 0.f;
#pragma unroll
    for (int i = 0; i < 16; i++) {
        int tk = lane + i*32;
        float dd = (float)tk / L - mu;
        float v = (tk <= tq) ? __expf(-dd*dd / denom) : 0.f;
        wv[i] = v; sum += v;
    }
#pragma unroll
    for (int o = 16; o; o >>= 1) sum += __shfl_xor_sync(0xffffffffu, sum, o);
    float inv = 1.f / fmaxf(sum, 1e-12f);
#pragma unroll
    for (int i = 0; i < 16; i++) grow[lane + i*32] = wv[i] * inv;
}

// ---------------- concat [ctx, enc] ----------------
__global__ void concat_kernel() {
    int idx = blockIdx.x * blockDim.x + threadIdx.x;
    if (idx >= MTOK * 128) return;
    int m = idx >> 7, h4 = idx & 127;
    float4 c4 = *reinterpret_cast<const float4*>(&d_ctx[((size_t)m << 9) + (h4 << 2)]);
    float4 e4 = *reinterpret_cast<const float4*>(&d_henc[((size_t)m << 9) + (h4 << 2)]);
    *reinterpret_cast<float4*>(&d_cat[(size_t)m*1024 + (h4 << 2)]) = c4;
    *reinterpret_cast<float4*>(&d_cat[(size_t)m*1024 + 512 + (h4 << 2)]) = e4;
}

// ---------------- fp32 -> split-bf16 (generic) ----------------
// A-side layout: [hi | hi | lo]; B-side layout: [hi | lo | hi].
__device__ __forceinline__ void split_bf16(float a, unsigned short& h, unsigned short& l) {
    __nv_bfloat16 hb = __float2bfloat16_rn(a);
    float lo = a - __bfloat162float(hb);
    __nv_bfloat16 lb = __float2bfloat16_rn(lo);
    h = *reinterpret_cast<unsigned short*>(&hb);
    l = *reinterpret_cast<unsigned short*>(&lb);
}

template<bool ASIDE>
__global__ void split_kernel(const float* __restrict__ X, __nv_bfloat16* __restrict__ Y, int K0) {
    int K4 = K0 >> 2;
    size_t i = (size_t)blockIdx.x * 256 + threadIdx.x;   // float4 index
    size_t r = i / (size_t)K4;
    int k4 = (int)(i % (size_t)K4) * 4;
    float4 v = *reinterpret_cast<const float4*>(&X[r * (size_t)K0 + k4]);
    unsigned short h[4], l[4];
    split_bf16(v.x, h[0], l[0]); split_bf16(v.y, h[1], l[1]);
    split_bf16(v.z, h[2], l[2]); split_bf16(v.w, h[3], l[3]);
    ushort4 H  = make_ushort4(h[0], h[1], h[2], h[3]);
    ushort4 Lo = make_ushort4(l[0], l[1], l[2], l[3]);
    __nv_bfloat16* base = Y + r * (size_t)(3*K0) + k4;
    *reinterpret_cast<ushort4*>(base)            = H;
    *reinterpret_cast<ushort4*>(base + K0)       = ASIDE ? H  : Lo;
    *reinterpret_cast<ushort4*>(base + 2*K0)     = ASIDE ? Lo : H;
}

// ---------------- unified bf16-split TC GEMM (3-stage cp.async pipeline) -------------------
__device__ __forceinline__ void ldsm_x4(uint32_t& r0, uint32_t& r1, uint32_t& r2, uint32_t& r3,
                                        uint32_t addr) {
    asm volatile("ldmatrix.sync.aligned.m8n8.x4.shared.b16 {%0,%1,%2,%3}, [%4];"
                 : "=r"(r0), "=r"(r1), "=r"(r2), "=r"(r3) : "r"(addr));
}
__device__ __forceinline__ void ldsm_x2(uint32_t& r0, uint32_t& r1, uint32_t addr) {
    asm volatile("ldmatrix.sync.aligned.m8n8.x2.shared.b16 {%0,%1}, [%2];"
                 : "=r"(r0), "=r"(r1) : "r"(addr));
}
__device__ __forceinline__ void mma_bf16(float* c, const uint32_t* a, const uint32_t* b) {
    asm volatile(
        "mma.sync.aligned.m16n8k16.row.col.f32.bf16.bf16.f32 "
        "{%0,%1,%2,%3}, {%4,%5,%6,%7}, {%8,%9}, {%0,%1,%2,%3};"
        : "+f"(c[0]), "+f"(c[1]), "+f"(c[2]), "+f"(c[3])
        : "r"(a[0]), "r"(a[1]), "r"(a[2]), "r"(a[3]), "r"(b[0]), "r"(b[1]));
}
__device__ __forceinline__ void cp_async16(uint32_t s, const void* g) {
    asm volatile("cp.async.cg.shared.global [%0], [%1], 16;" :: "r"(s), "l"(g));
}
#define CP_COMMIT() asm volatile("cp.async.commit_group;" ::: "memory")

#define TCSTG (128*40)                 // elements per stage per operand
#define TC_SMEM (3 * TCSTG * 2 * 2)    // bytes: 3 stages x 2 operands x bf16

// BM=BN=128, BK=32, 256 threads (8 warps 2x4), warp tile 64x32. M,N mult of 128, KD mult of 32.
// grid = dim3(M/128, N/128): blockIdx.x = m tile (fast) so waves share B tiles.
template<int ACT>
__global__ __launch_bounds__(256) void tc_gemm_nt(
    const __nv_bfloat16* __restrict__ A, const __nv_bfloat16* __restrict__ B,
    const float* __restrict__ b1, const float* __restrict__ b2,
    float* __restrict__ C, int N, int KDp)
{
    extern __shared__ __align__(16) char smem_raw[];
    __nv_bfloat16* Asm = reinterpret_cast<__nv_bfloat16*>(smem_raw);
    __nv_bfloat16* Bsm = Asm + 3 * TCSTG;

    int tid = threadIdx.x, lane = tid & 31, w = tid >> 5;
    int wm = w >> 2, wn = w & 3;
    int m0 = blockIdx.x * 128, n0 = blockIdx.y * 128;
    int lr = tid >> 2;
    int lc = (tid & 3) * 8;
    const __nv_bfloat16* Ag = A + (size_t)(m0 + lr) * KDp + lc;
    const __nv_bfloat16* Bg = B + (size_t)(n0 + lr) * KDp + lc;

    uint32_t sA = (uint32_t)__cvta_generic_to_shared(Asm);
    uint32_t sB = (uint32_t)__cvta_generic_to_shared(Bsm);
    uint32_t offLo = (uint32_t)(lr * 40 + lc) * 2;
    uint32_t offHi = (uint32_t)((lr + 64) * 40 + lc) * 2;

    int iters = KDp >> 5;

    float acc[4][4][4];
#pragma unroll
    for (int i = 0; i < 4; i++)
#pragma unroll
        for (int j = 0; j < 4; j++) { acc[i][j][0]=0.f; acc[i][j][1]=0.f; acc[i][j][2]=0.f; acc[i][j][3]=0.f; }

    // prologue: stages 0,1
#pragma unroll
    for (int s = 0; s < 2; s++) {
        uint32_t sa = sA + (uint32_t)s * TCSTG * 2;
        uint32_t sb = sB + (uint32_t)s * TCSTG * 2;
        cp_async16(sa + offLo, Ag + s * 32);
        cp_async16(sa + offHi, Ag + s * 32 + (size_t)64 * KDp);
        cp_async16(sb + offLo, Bg + s * 32);
        cp_async16(sb + offHi, Bg + s * 32 + (size_t)64 * KDp);
        CP_COMMIT();
    }

    for (int kt = 0; kt < iters; kt++) {
        asm volatile("cp.async.wait_group 1;" ::: "memory");  // stage kt done (this thread)
        __syncthreads();                                      // all threads' loads visible
        int nxt = kt + 2;
        if (nxt < iters) {                                    // refill stage (kt-1)%3 slot
            int nb = nxt % 3;
            uint32_t sa = sA + (uint32_t)nb * TCSTG * 2;
            uint32_t sb = sB + (uint32_t)nb * TCSTG * 2;
            cp_async16(sa + offLo, Ag + nxt * 32);
            cp_async16(sa + offHi, Ag + nxt * 32 + (size_t)64 * KDp);
            cp_async16(sb + offLo, Bg + nxt * 32);
            cp_async16(sb + offHi, Bg + nxt * 32 + (size_t)64 * KDp);
        }
        CP_COMMIT();                                          // commit (possibly empty) group

        int buf = kt % 3;
        uint32_t sAb = sA + (uint32_t)buf * TCSTG * 2;
        uint32_t sBb = sB + (uint32_t)buf * TCSTG * 2;
#pragma unroll
        for (int k16 = 0; k16 < 2; k16++) {
            uint32_t af[4][4], bf[4][2];
#pragma unroll
            for (int mt = 0; mt < 4; mt++) {
                uint32_t addr = sAb + ((wm*64 + mt*16 + (lane & 15)) * 40 + k16*16 + (lane >> 4)*8) * 2;
                ldsm_x4(af[mt][0], af[mt][1], af[mt][2], af[mt][3], addr);
            }
#pragma unroll
            for (int nt = 0; nt < 4; nt++) {
                uint32_t addr = sBb + ((wn*32 + nt*8 + (lane & 7)) * 40 + k16*16 + ((lane >> 3) & 1)*8) * 2;
                ldsm_x2(bf[nt][0], bf[nt][1], addr);
            }
#pragma unroll
            for (int mt = 0; mt < 4; mt++)
#pragma unroll
                for (int nt = 0; nt < 4; nt++)
                    mma_bf16(acc[mt][nt], af[mt], bf[nt]);
        }
    }

    // epilogue: bias (b1 [+ b2]), optional tanh, fp32 store
#pragma unroll
    for (int mt = 0; mt < 4; mt++) {
        int r0 = m0 + wm*64 + mt*16 + (lane >> 2);
#pragma unroll
        for (int nt = 0; nt < 4; nt++) {
            int cc = n0 + wn*32 + nt*8 + (lane & 3)*2;
            float bb0 = b1[cc],     bb1 = b1[cc + 1];
            if (b2) { bb0 += b2[cc]; bb1 += b2[cc + 1]; }
            float v00 = acc[mt][nt][0] + bb0, v01 = acc[mt][nt][1] + bb1;
            float v10 = acc[mt][nt][2] + bb0, v11 = acc[mt][nt][3] + bb1;
            if (ACT == 1) { v00 = tanhf(v00); v01 = tanhf(v01); v10 = tanhf(v10); v11 = tanhf(v11); }
            *reinterpret_cast<float2*>(&C[(size_t)r0 * N + cc])       = make_float2(v00, v01);
            *reinterpret_cast<float2*>(&C[(size_t)(r0 + 8) * N + cc]) = make_float2(v10, v11);
        }
    }
}

// ---------------- launcher ----------------
extern "C" void kernel_launch(void* const* d_in, const int* in_sizes, int n_in,
                              void* d_out, int out_size)
{
    const int*   tokens   = (const int*)d_in[0];
    const int*   pad_len  = (const int*)d_in[1];
    const float* embedding= (const float*)d_in[2];
    const float* enc_Wih  = (const float*)d_in[3];
    const float* enc_Whh  = (const float*)d_in[4];
    const float* enc_bih  = (const float*)d_in[5];
    const float* enc_bhh  = (const float*)d_in[6];
    const float* pos_Wih  = (const float*)d_in[7];
    const float* pos_Whh  = (const float*)d_in[8];
    const float* pos_bih  = (const float*)d_in[9];
    const float* pos_bhh  = (const float*)d_in[10];
    const float* W_mu     = (const float*)d_in[11];
    const float* b_mu     = (const float*)d_in[12];
    const float* W_sig    = (const float*)d_in[13];
    const float* b_sig    = (const float*)d_in[14];
    const float* W_cat    = (const float*)d_in[15];
    const float* b_cat    = (const float*)d_in[16];
    const float* dec_b    = (const float*)d_in[17];
    float* out = (float*)d_out;

    float *p_emb, *p_xg_enc, *p_henc, *p_xg_pos, *p_gw, *p_ctx, *p_cat, *p_comb;
    __nv_bfloat16 *p_A2, *p_B2, *p_W2ih, *p_cat2, *p_Wcat2;
    cudaGetSymbolAddress((void**)&p_emb,    d_emb);
    cudaGetSymbolAddress((void**)&p_xg_enc, d_xg_enc);
    cudaGetSymbolAddress((void**)&p_henc,   d_henc);
    cudaGetSymbolAddress((void**)&p_xg_pos, d_xg_pos);
    cudaGetSymbolAddress((void**)&p_gw,     d_gw);
    cudaGetSymbolAddress((void**)&p_ctx,    d_ctx);
    cudaGetSymbolAddress((void**)&p_cat,    d_cat);
    cudaGetSymbolAddress((void**)&p_comb,   d_comb);
    cudaGetSymbolAddress((void**)&p_A2,     d_A2);
    cudaGetSymbolAddress((void**)&p_B2,     d_B2);
    cudaGetSymbolAddress((void**)&p_W2ih,   d_W2ih);
    cudaGetSymbolAddress((void**)&p_cat2,   d_cat2);
    cudaGetSymbolAddress((void**)&p_Wcat2,  d_Wcat2);

    cudaFuncSetAttribute(tc_gemm_nt<0>, cudaFuncAttributeMaxDynamicSharedMemorySize, TC_SMEM);
    cudaFuncSetAttribute(tc_gemm_nt<1>, cudaFuncAttributeMaxDynamicSharedMemorySize, TC_SMEM);

    // 1) gather embeddings; independent splits
    gather_kernel<<<MTOK, 128>>>(tokens, embedding);
    split_kernel<false><<<(VV*128)/256, 256>>>(embedding, p_B2, HH);        // decoder B
    split_kernel<false><<<(G4H*128)/256, 256>>>(enc_Wih, p_W2ih, HH);       // Wih
    split_kernel<true ><<<(MTOK*128)/256, 256>>>(p_emb, p_A2, HH);          // emb_g (A side)
    // 2) xg_enc = emb @ Wih^T + bih + bhh  (TC)
    tc_gemm_nt<0><<<dim3(MTOK/128, G4H/128), 256, TC_SMEM>>>(
        p_A2, p_W2ih, enc_bih, enc_bhh, p_xg_enc, G4H, 1536);
    // 3) encoder LSTM: init + 512 sequential step launches
    enc_init_kernel<<<(BB*HH + 255)/256, 256>>>();
    for (int t = 0; t < TT; t++)
        enc_step_kernel<<<128, 256>>>(t, p_xg_enc, enc_Whh);
    // 4) xg_pos = henc @ pos_Wih^T + biases (fp32, guarded small-N)
    gemm_nt_kernel<0,true><<<dim3(1, MTOK/128), 256>>>(
        p_henc, pos_Wih, pos_bih, pos_bhh, p_xg_pos, MTOK, G4P, HH);
    // 5) pos LSTM + heads + mu scan
    pos_kernel<<<BB, 128>>>(pad_len, pos_Whh, W_mu, b_mu, W_sig, b_sig);
    // 6) attention weights
    attn_kernel<<<(BB*TT)/8, 256>>>(pad_len);
    // 7) ctx = g @ enc
    gemm_nn_kernel<<<dim3(HH/128, TT/128, BB), 256>>>(
        p_gw, p_henc, p_ctx, TT, HH, TT,
        (size_t)TT*TT, (size_t)TT*HH, (size_t)TT*HH);
    // 8) concat + splits for comb GEMM
    concat_kernel<<<(MTOK*128)/256, 256>>>();
    split_kernel<true ><<<(MTOK*256)/256, 256>>>(p_cat, p_cat2, 2*HH);
    split_kernel<false><<<(HH*256)/256, 256>>>(W_cat, p_Wcat2, 2*HH);
    // 9) comb = tanh(cat @ W_cat^T + b_cat)  (TC)
    tc_gemm_nt<1><<<dim3(MTOK/128, HH/128), 256, TC_SMEM>>>(
        p_cat2, p_Wcat2, b_cat, nullptr, p_comb, HH, 3072);
    // 10) decoder: split comb, logits = comb @ emb^T + dec_b  (TC)
    split_kernel<true><<<(MTOK*128)/256, 256>>>(p_comb, p_A2, HH);
    tc_gemm_nt<0><<<dim3(MTOK/128, VV/128), 256, TC_SMEM>>>(
        p_A2, p_B2, dec_b, nullptr, out, VV, 1536);

    (void)in_sizes; (void)n_in; (void)out_size;
}